// round 11
// baseline (speedup 1.0000x reference)
#include <cuda_runtime.h>
#include <cuda_fp16.h>
#include <math.h>

// Problem constants
#define BATCH   4
#define TT      4096
#define EE      2048
#define DD      1024
#define GDIM    4096          // 4*DD gate rows
#define MOUT    2
#define KINW    2048          // input width per layer (E for l0, 2*DD for l1)

// Recurrence persistent-kernel config
#define RGRID    148          // <= SM count -> guaranteed co-resident
#define RTHREADS 256
#define NUNITS   (2*DD)       // dirs * D hidden units
#define UPB      ((NUNITS + RGRID - 1)/RGRID)   // 14 units per block

// ---------------- scratch (static device arrays only; no allocation) ------
__device__ __align__(128) float g_x   [BATCH*TT*KINW];      // layer input
__device__ __align__(128) float g_gx  [2u*BATCH*TT*GDIM];   // preacts [d][b][t][j][gate]
__device__ __align__(128) float g_hL  [BATCH*TT*DD];
__device__ __align__(128) float g_hR  [BATCH*TT*DD];
__device__ __align__(128) float g_hcur[2][2*BATCH*DD];      // double-buffered current h
__device__ __align__(128) __half2 g_whhc[2*2*1024*512*4];   // fp16 Whh, [ld][j][kp][gate]
__device__ __align__(128) unsigned g_flags[RGRID*32];       // barrier arrival flags (128B stride)
__device__ float g_wv  [BATCH*TT];
__device__ float g_att [BATCH*TT];
__device__ float g_ctxtL[BATCH*DD];
__device__ float g_ctxtR[BATCH*DD];
__device__ unsigned int g_barEpoch;

// ---------------- packed f32x2 FMA helpers ----------------
__device__ __forceinline__ void fma2u(unsigned long long& d, unsigned long long a, unsigned long long b) {
    asm("fma.rn.f32x2 %0, %1, %2, %0;" : "+l"(d) : "l"(a), "l"(b));
}
__device__ __forceinline__ unsigned long long dup2(float v) {
    unsigned long long r; unsigned u = __float_as_uint(v);
    asm("mov.b64 %0, {%1, %1};" : "=l"(r) : "r"(u));
    return r;
}
__device__ __forceinline__ void fma2f(float2& d, float2 a, float2 b) {
    asm("fma.rn.f32x2 %0, %1, %2, %0;"
        : "+l"(reinterpret_cast<unsigned long long&>(d))
        : "l"(reinterpret_cast<unsigned long long&>(a)),
          "l"(reinterpret_cast<unsigned long long&>(b)));
}

// ---------------- scoped release/acquire primitives (no CCTL.IVALL) -------
__device__ __forceinline__ unsigned ld_acq(unsigned* p) {
    unsigned v; asm volatile("ld.acquire.gpu.u32 %0, [%1];" : "=r"(v) : "l"(p) : "memory"); return v;
}
__device__ __forceinline__ void st_rel(unsigned* p, unsigned v) {
    asm volatile("st.release.gpu.u32 [%0], %1;" :: "l"(p), "r"(v) : "memory");
}

// ---------------- grid-wide barrier: per-block flags + single aggregator ---
// No same-address atomics (148 serialized ATOMGs cost ~5K cyc). Each block
// release-stores its own 128B-stride flag; block 0's first 148 threads each
// acquire-poll one flag, then one thread release-stores the epoch.
// Epochs are monotone; (int)(v - e) >= 0 compare makes flag reuse safe.
__device__ __forceinline__ void grid_barrier(unsigned* localEpoch) {
    const unsigned e = *localEpoch + 1u;
    __syncthreads();
    if (threadIdx.x == 0)
        st_rel(&g_flags[blockIdx.x * 32], e);
    if (blockIdx.x == 0) {
        if (threadIdx.x < RGRID) {
            unsigned* f = &g_flags[threadIdx.x * 32];
            while ((int)(ld_acq(f) - e) < 0) { __nanosleep(32); }
        }
        __syncthreads();
        if (threadIdx.x == 0) st_rel(&g_barEpoch, e);
    } else {
        if (threadIdx.x == 0) {
            while ((int)(ld_acq(&g_barEpoch) - e) < 0) { __nanosleep(32); }
        }
        __syncthreads();
    }
    *localEpoch = e;
}

// ---------------- embedding gather ----------------
__global__ void k_embed(const int* __restrict__ toks, const float* __restrict__ emb) {
    int idx = blockIdx.x * blockDim.x + threadIdx.x;      // float4 granularity
    const int total = BATCH*TT*(EE/4);
    if (idx >= total) return;
    int row = idx / (EE/4);
    int c   = idx - row*(EE/4);
    int tok = toks[row];
    reinterpret_cast<float4*>(g_x)[idx] =
        reinterpret_cast<const float4*>(emb + (size_t)tok*EE)[c];
}

// ---------------- Whh -> fp16 gate-interleaved: [ld][j][kp][g] -------------
__global__ void k_wconv(const float* __restrict__ Whh) {
    int idx = blockIdx.x * blockDim.x + threadIdx.x;      // over 2*2*1024*512
    const int total = 2*2*1024*512;
    if (idx >= total) return;
    int kp = idx & 511;
    int j  = (idx >> 9) & 1023;
    int ld = idx >> 19;
    const float* Wl = Whh + (size_t)ld * GDIM * DD;
    __half2* outp = g_whhc + (size_t)idx * 4;
    #pragma unroll
    for (int g = 0; g < 4; ++g) {
        const float* wr = Wl + (size_t)(g*DD + j)*DD + 2*kp;
        outp[g] = __floats2half2_rn(wr[0], wr[1]);
    }
}

// ---------------- gx GEMM -> gate-interleaved preacts ----------------------
// out[d][b][s][j][gate] = x[b][srow] . W[gate*DD+j] + bias;  srow = d ? T-1-s : s
__global__ __launch_bounds__(256) void k_gemm(const float* __restrict__ Wxh,
                                              const float* __restrict__ bxh,
                                              const float* __restrict__ bhh,
                                              int layer) {
    const int d     = blockIdx.z;
    const int nBase = blockIdx.x * 64;
    const int mBase = blockIdx.y * 128;

    const float* W  = Wxh + (size_t)(layer*2 + d) * GDIM * KINW;
    const float* bx = bxh + (size_t)(layer*2 + d) * GDIM;
    const float* bh = bhh + (size_t)(layer*2 + d) * GDIM;

    __shared__ float As[16][128];
    __shared__ float Bs[16][64];

    const int tid  = threadIdx.x;
    const int aRow = tid >> 1;            // 0..127
    const int aKc  = (tid & 1) * 8;       // 0 or 8
    const int wRow = tid & 63;            // 0..63
    const int wKc  = (tid >> 6) * 4;      // 0,4,8,12

    const int bIdx  = mBase >> 12;        // T=4096: a 128-row tile never crosses batch
    const int sBase = mBase & (TT-1);

    const float* Arow;
    {
        int s    = sBase + aRow;
        int srow = d ? (TT-1-s) : s;
        Arow = g_x + ((size_t)bIdx*TT + srow)*KINW;
    }
    const float* Wrow = W + (size_t)(nBase + wRow)*KINW;

    // accumulators: pair p covers rows ty*8+2p, ty*8+2p+1 (lo, hi)
    unsigned long long accp[4][4];
    #pragma unroll
    for (int p=0;p<4;p++)
        #pragma unroll
        for (int j=0;j<4;j++) accp[p][j] = 0ull;

    const int ty = tid >> 4;   // 0..15, 8 M-rows each
    const int tx = tid & 15;   // 0..15, 4 N-cols each

    float4 ca0 = *reinterpret_cast<const float4*>(Arow + aKc);
    float4 ca1 = *reinterpret_cast<const float4*>(Arow + aKc + 4);
    float4 cw0 = *reinterpret_cast<const float4*>(Wrow + wKc);

    for (int k0 = 0; k0 < KINW; k0 += 16) {
        As[aKc+0][aRow]=ca0.x; As[aKc+1][aRow]=ca0.y; As[aKc+2][aRow]=ca0.z; As[aKc+3][aRow]=ca0.w;
        As[aKc+4][aRow]=ca1.x; As[aKc+5][aRow]=ca1.y; As[aKc+6][aRow]=ca1.z; As[aKc+7][aRow]=ca1.w;
        Bs[wKc+0][wRow]=cw0.x; Bs[wKc+1][wRow]=cw0.y; Bs[wKc+2][wRow]=cw0.z; Bs[wKc+3][wRow]=cw0.w;
        __syncthreads();

        const int kn = (k0 + 16 < KINW) ? (k0 + 16) : 0;   // harmless dummy reload on last iter
        ca0 = *reinterpret_cast<const float4*>(Arow + kn + aKc);
        ca1 = *reinterpret_cast<const float4*>(Arow + kn + aKc + 4);
        cw0 = *reinterpret_cast<const float4*>(Wrow + kn + wKc);

        #pragma unroll
        for (int kk = 0; kk < 16; ++kk) {
            const unsigned long long* ap =
                reinterpret_cast<const unsigned long long*>(&As[kk][ty*8]);
            unsigned long long a0 = ap[0], a1 = ap[1], a2 = ap[2], a3 = ap[3];
            float4 fb = *reinterpret_cast<const float4*>(&Bs[kk][tx*4]);
            unsigned long long b0 = dup2(fb.x), b1 = dup2(fb.y),
                               b2 = dup2(fb.z), b3 = dup2(fb.w);
            fma2u(accp[0][0], a0, b0); fma2u(accp[0][1], a0, b1);
            fma2u(accp[0][2], a0, b2); fma2u(accp[0][3], a0, b3);
            fma2u(accp[1][0], a1, b0); fma2u(accp[1][1], a1, b1);
            fma2u(accp[1][2], a1, b2); fma2u(accp[1][3], a1, b3);
            fma2u(accp[2][0], a2, b0); fma2u(accp[2][1], a2, b1);
            fma2u(accp[2][2], a2, b2); fma2u(accp[2][3], a2, b3);
            fma2u(accp[3][0], a3, b0); fma2u(accp[3][1], a3, b1);
            fma2u(accp[3][2], a3, b2); fma2u(accp[3][3], a3, b3);
        }
        __syncthreads();
    }

    float bias[4];
    #pragma unroll
    for (int j=0;j<4;j++) bias[j] = bx[nBase+tx*4+j] + bh[nBase+tx*4+j];

    // interleaved epilogue: addr = row*4096 + j*4 + gate  (whole tile is one gate)
    const int gate = nBase >> 10;
    const int jB   = (nBase & 1023) + tx*4;

    #pragma unroll
    for (int i=0;i<8;i++) {
        size_t rowbase = ((size_t)(d*BATCH + bIdx)*TT + sBase + ty*8 + i)*(size_t)GDIM;
        #pragma unroll
        for (int j=0;j<4;j++) {
            unsigned long long q = accp[i>>1][j];
            unsigned u = (i & 1) ? (unsigned)(q >> 32) : (unsigned)q;
            g_gx[rowbase + (size_t)(jB + j)*4 + gate] = __uint_as_float(u) + bias[j];
        }
    }
}

// ---------------- persistent biLSTM recurrence over T steps ----------------
__global__ __launch_bounds__(RTHREADS) void k_recur(int layer) {
    __shared__ float h_sm[2*BATCH*DD];   // 32 KB: [d][b][k]; only owned dir staged
    const int tid  = threadIdx.x;
    const int warp = tid >> 5;
    const int lane = tid & 31;

    unsigned int localEpoch = ld_acq(&g_barEpoch);

    // zero h buffer 0 (read at t=0)
    for (int i = blockIdx.x*RTHREADS + tid; i < 2*BATCH*DD; i += RGRID*RTHREADS)
        g_hcur[0][i] = 0.f;
    grid_barrier(&localEpoch);

    const int u0 = blockIdx.x * UPB;
    int nLocal = NUNITS - u0;
    if (nLocal > UPB) nLocal = UPB;
    if (nLocal < 0)   nLocal = 0;

    // stage range: only the direction(s) this block's units live in
    int stage_base = 0, stage_q = 0;   // float4 units
    if (nLocal > 0) {
        int d_lo = u0 >> 10;
        int d_hi = (u0 + nLocal - 1) >> 10;
        stage_base = d_lo * (BATCH*DD/4);
        stage_q    = (d_hi - d_lo + 1) * (BATCH*DD/4);
    }

    // per-warp unit setup: warp owns local units {warp, warp+8}
    const uint4* wq[2];
    const float2* hp2[2];
    int jj[2], dd_[2], valid[2];
    #pragma unroll
    for (int r=0;r<2;r++) {
        int lu = warp + 8*r;
        valid[r] = (lu < nLocal);
        int u = u0 + (valid[r] ? lu : 0);
        if (u >= NUNITS) u = 0;           // inert blocks: keep pointers in range
        int d = u >> 10;
        int j = u & (DD-1);
        dd_[r] = d; jj[r] = j;
        wq[r]  = reinterpret_cast<const uint4*>(
                     g_whhc + ((size_t)((layer*2 + d)*1024 + j) * 512) * 4);
        hp2[r] = reinterpret_cast<const float2*>(h_sm + d*BATCH*DD);
    }
    float creg[2] = {0.f, 0.f};   // cell state: lane b holds batch b
    const float4* gx4 = reinterpret_cast<const float4*>(g_gx);

    for (int t = 0; t < TT; ++t) {
        const int rb = t & 1;          // read buffer
        const int wb = rb ^ 1;         // write buffer

        // prefetch gate preacts (one LDG.128 per unit per batch-lane; DRAM
        // latency hides under staging + FMA loop)
        float4 pre[2];
        #pragma unroll
        for (int r=0;r<2;r++)
            if (lane < BATCH)
                pre[r] = __ldcg(gx4 + ((size_t)(dd_[r]*BATCH + lane)*TT + t)*DD + jj[r]);

        // stage h via L2 (other SMs wrote it last step; L1 may be stale)
        {
            const float4* src = reinterpret_cast<const float4*>(g_hcur[rb]) + stage_base;
            float4* dst = reinterpret_cast<float4*>(h_sm) + stage_base;
            for (int i = tid; i < stage_q; i += RTHREADS)
                dst[i] = __ldcg(src + i);
        }
        __syncthreads();

        #pragma unroll
        for (int r = 0; r < 2; ++r) {
            if (!valid[r]) continue;
            const uint4* w = wq[r];
            const float2* hp = hp2[r];

            float2 acc2[4][4];
            #pragma unroll
            for (int g=0;g<4;g++)
                #pragma unroll
                for (int b=0;b<4;b++) acc2[g][b] = make_float2(0.f, 0.f);

            #pragma unroll
            for (int it = 0; it < 16; ++it) {
                int kp = it*32 + lane;
                uint4 wv = w[kp];                 // 4 gates x half2 (2 k), one LDG.128
                float2 w0 = __half22float2(*reinterpret_cast<__half2*>(&wv.x));
                float2 w1 = __half22float2(*reinterpret_cast<__half2*>(&wv.y));
                float2 w2 = __half22float2(*reinterpret_cast<__half2*>(&wv.z));
                float2 w3 = __half22float2(*reinterpret_cast<__half2*>(&wv.w));
                float2 h0 = hp[0*512 + kp];
                float2 h1 = hp[1*512 + kp];
                float2 h2 = hp[2*512 + kp];
                float2 h3 = hp[3*512 + kp];
                fma2f(acc2[0][0], w0, h0); fma2f(acc2[0][1], w0, h1);
                fma2f(acc2[0][2], w0, h2); fma2f(acc2[0][3], w0, h3);
                fma2f(acc2[1][0], w1, h0); fma2f(acc2[1][1], w1, h1);
                fma2f(acc2[1][2], w1, h2); fma2f(acc2[1][3], w1, h3);
                fma2f(acc2[2][0], w2, h0); fma2f(acc2[2][1], w2, h1);
                fma2f(acc2[2][2], w2, h2); fma2f(acc2[2][3], w2, h3);
                fma2f(acc2[3][0], w3, h0); fma2f(acc2[3][1], w3, h1);
                fma2f(acc2[3][2], w3, h2); fma2f(acc2[3][3], w3, h3);
            }

            float acc[4][4];
            #pragma unroll
            for (int g=0;g<4;g++)
                #pragma unroll
                for (int b=0;b<4;b++) {
                    float s = acc2[g][b].x + acc2[g][b].y;
                    #pragma unroll
                    for (int off=16; off>0; off>>=1)
                        s += __shfl_xor_sync(0xffffffffu, s, off);
                    acc[g][b] = s;
                }

            const int d = dd_[r];
            const int j = jj[r];
            if (lane < BATCH) {
                const int bb = lane;
                float pi = acc[0][bb] + pre[r].x;
                float pg = acc[1][bb] + pre[r].y;
                float pf = acc[2][bb] + pre[r].z;
                float po = acc[3][bb] + pre[r].w;
                float ii = 1.f/(1.f + expf(-pi));
                float gg = tanhf(pg);
                float ff = 1.f/(1.f + expf(-pf));
                float oo = 1.f/(1.f + expf(-po));
                float c  = ff*creg[r] + ii*gg;
                creg[r]  = c;
                float h  = oo * tanhf(c);
                g_hcur[wb][(d*BATCH + bb)*DD + j] = h;
                float* hist = (d == 0) ? g_hL : g_hR;
                hist[((size_t)bb*TT + t)*DD + j] = h;
            }
        }
        grid_barrier(&localEpoch);
    }
}

// ---------------- layer-1 input: x[b][t] = [hL[b][t], hR[b][T-1-t]] --------
__global__ void k_concat() {
    int idx = blockIdx.x * blockDim.x + threadIdx.x;    // float4 granularity
    const int total = BATCH*TT*(KINW/4);
    if (idx >= total) return;
    int c   = idx & (KINW/4 - 1);
    int row = idx >> 9;                 // KINW/4 = 512
    int b   = row >> 12;
    int t   = row & (TT-1);
    float4 v;
    if (c < DD/4) {
        v = reinterpret_cast<const float4*>(g_hL + ((size_t)b*TT + t)*DD)[c];
    } else {
        v = reinterpret_cast<const float4*>(g_hR + ((size_t)b*TT + (TT-1-t))*DD)[c - DD/4];
    }
    reinterpret_cast<float4*>(g_x)[idx] = v;
}

// ---------------- attention logits -----------------------------------------
__global__ void k_dots() {
    const int b = blockIdx.x >> 12;
    const int t = blockIdx.x & (TT-1);
    const int tid = threadIdx.x;
    const float* hl  = g_hL + ((size_t)b*TT + t)*DD;
    const float* hll = g_hL + ((size_t)b*TT + (TT-1))*DD;
    const float* hr  = g_hR + ((size_t)b*TT + t)*DD;
    const float* hrl = g_hR + ((size_t)b*TT + (TT-1))*DD;
    float s = 0.f;
    for (int j = tid; j < DD; j += 256)
        s += hl[j]*hll[j] + hr[j]*hrl[j];
    #pragma unroll
    for (int o=16;o>0;o>>=1) s += __shfl_xor_sync(0xffffffffu, s, o);
    __shared__ float red[8];
    if ((tid & 31) == 0) red[tid>>5] = s;
    __syncthreads();
    if (tid == 0) {
        float v = 0.f;
        #pragma unroll
        for (int w=0;w<8;w++) v += red[w];
        g_wv[(size_t)b*TT + t] = v * (1.f/64.f);   // 1/sqrt(4096)
    }
}

// ---------------- softmax per batch -----------------------------------------
__global__ void k_softmax() {
    const int b = blockIdx.x, tid = threadIdx.x;   // 1024 threads
    __shared__ float red[32];
    __shared__ float sval;
    const float* w = g_wv + (size_t)b*TT;
    float m = -1e30f;
    for (int t = tid; t < TT; t += 1024) m = fmaxf(m, w[t]);
    #pragma unroll
    for (int o=16;o>0;o>>=1) m = fmaxf(m, __shfl_xor_sync(0xffffffffu, m, o));
    if ((tid&31)==0) red[tid>>5] = m;
    __syncthreads();
    if (tid < 32) {
        float v = red[tid];
        #pragma unroll
        for (int o=16;o>0;o>>=1) v = fmaxf(v, __shfl_xor_sync(0xffffffffu, v, o));
        if (tid==0) sval = v;
    }
    __syncthreads();
    m = sval;
    float s = 0.f;
    for (int t = tid; t < TT; t += 1024) {
        float e = expf(w[t] - m);
        g_att[(size_t)b*TT + t] = e;
        s += e;
    }
    #pragma unroll
    for (int o=16;o>0;o>>=1) s += __shfl_xor_sync(0xffffffffu, s, o);
    __syncthreads();
    if ((tid&31)==0) red[tid>>5] = s;
    __syncthreads();
    if (tid < 32) {
        float v = red[tid];
        #pragma unroll
        for (int o=16;o>0;o>>=1) v += __shfl_xor_sync(0xffffffffu, v, o);
        if (tid==0) sval = v;
    }
    __syncthreads();
    float inv = 1.f / sval;
    for (int t = tid; t < TT; t += 1024)
        g_att[(size_t)b*TT + t] *= inv;
}

// ---------------- context vectors -------------------------------------------
__global__ void k_ctxt() {
    const int b = blockIdx.y;
    const int j = blockIdx.x*128 + threadIdx.x;
    const float* att = g_att + (size_t)b*TT;
    float aL = 0.f, aR = 0.f;
    for (int t = 0; t < TT; t += 4) {
        float a0 = att[t], a1 = att[t+1], a2 = att[t+2], a3 = att[t+3];
        const float* hl = g_hL + ((size_t)b*TT + t)*DD + j;
        const float* hr = g_hR + ((size_t)b*TT + t)*DD + j;
        aL += a0*hl[0] + a1*hl[DD] + a2*hl[2*DD] + a3*hl[3*DD];
        aR += a0*hr[0] + a1*hr[DD] + a2*hr[2*DD] + a3*hr[3*DD];
    }
    g_ctxtL[b*DD + j] = aL;
    g_ctxtR[b*DD + j] = aR;
}

// ---------------- output: out[b][m] = WcyL[m].ctxtL[b] + WcyR[m].ctxtR[b] ---
__global__ void k_out(const float* __restrict__ WcyL, const float* __restrict__ WcyR,
                      float* __restrict__ out) {
    const int b = blockIdx.x;
    const int m = threadIdx.x >> 5;     // 2 warps
    const int lane = threadIdx.x & 31;
    float s = 0.f;
    for (int j = lane; j < DD; j += 32)
        s += WcyL[m*DD + j]*g_ctxtL[b*DD + j] + WcyR[m*DD + j]*g_ctxtR[b*DD + j];
    #pragma unroll
    for (int o=16;o>0;o>>=1) s += __shfl_xor_sync(0xffffffffu, s, o);
    if (lane == 0) out[b*MOUT + m] = s;
}

// ---------------- launcher ---------------------------------------------------
extern "C" void kernel_launch(void* const* d_in, const int* in_sizes, int n_in,
                              void* d_out, int out_size) {
    const int*   toks = (const int*)  d_in[0];
    const float* emb  = (const float*)d_in[1];
    const float* Wxh  = (const float*)d_in[2];
    const float* Whh  = (const float*)d_in[3];
    const float* bxh  = (const float*)d_in[4];
    const float* bhh  = (const float*)d_in[5];
    const float* WcyL = (const float*)d_in[6];
    const float* WcyR = (const float*)d_in[7];
    float* out = (float*)d_out;
    (void)in_sizes; (void)n_in; (void)out_size;

    k_embed<<<(BATCH*TT*(EE/4) + 255)/256, 256>>>(toks, emb);
    k_wconv<<<(2*2*1024*512 + 255)/256, 256>>>(Whh);

    for (int layer = 0; layer < 2; ++layer) {
        dim3 ggrid(GDIM/64, (BATCH*TT)/128, 2);
        k_gemm<<<ggrid, 256>>>(Wxh, bxh, bhh, layer);
        k_recur<<<RGRID, RTHREADS>>>(layer);
        if (layer == 0)
            k_concat<<<(BATCH*TT*(KINW/4) + 255)/256, 256>>>();
    }

    k_dots<<<BATCH*TT, 256>>>();
    k_softmax<<<BATCH, 1024>>>();
    dim3 cgrid(DD/128, BATCH);
    k_ctxt<<<cgrid, 128>>>();
    k_out<<<BATCH, 64>>>(WcyL, WcyR, out);
}

// round 12
// speedup vs baseline: 1.2865x; 1.2865x over previous
#include <cuda_runtime.h>
#include <cuda_fp16.h>
#include <math.h>

// Problem constants
#define BATCH   4
#define TT      4096
#define EE      2048
#define DD      1024
#define GDIM    4096          // 4*DD gate rows
#define MOUT    2
#define KINW    2048          // input width per layer (E for l0, 2*DD for l1)

// Recurrence persistent-kernel config
#define RGRID    148
#define RTHREADS 256
#define NUNITS   (2*DD)
#define UPB      ((NUNITS + RGRID - 1)/RGRID)   // 14

// ---------------- scratch (static device arrays only; no allocation) ------
__device__ __align__(128) __half  g_xh  [BATCH*TT*KINW];      // fp16 layer input
__device__ __align__(128) __half  g_wxh16[2u*2u*GDIM*KINW];   // fp16 Wxh
__device__ __align__(128) float g_gx  [2u*BATCH*TT*GDIM];     // preacts [d][b][t][j][gate]
__device__ __align__(128) float g_hL  [BATCH*TT*DD];
__device__ __align__(128) float g_hR  [BATCH*TT*DD];
__device__ __align__(128) float g_hcur[2][2*BATCH*DD];
__device__ __align__(128) __half2 g_whhc[2*2*1024*512*4];     // fp16 Whh [ld][j][kp][gate]
__device__ __align__(128) unsigned g_flags[RGRID*32];
__device__ float g_wv  [BATCH*TT];
__device__ float g_att [BATCH*TT];
__device__ float g_ctxtL[BATCH*DD];
__device__ float g_ctxtR[BATCH*DD];
__device__ unsigned int g_barEpoch;

// ---------------- packed f32x2 FMA (recurrence) ----------------
__device__ __forceinline__ void fma2f(float2& d, float2 a, float2 b) {
    asm("fma.rn.f32x2 %0, %1, %2, %0;"
        : "+l"(reinterpret_cast<unsigned long long&>(d))
        : "l"(reinterpret_cast<unsigned long long&>(a)),
          "l"(reinterpret_cast<unsigned long long&>(b)));
}

// ---------------- scoped release/acquire primitives -----------------------
__device__ __forceinline__ unsigned ld_acq(unsigned* p) {
    unsigned v; asm volatile("ld.acquire.gpu.u32 %0, [%1];" : "=r"(v) : "l"(p) : "memory"); return v;
}
__device__ __forceinline__ void st_rel(unsigned* p, unsigned v) {
    asm volatile("st.release.gpu.u32 [%0], %1;" :: "l"(p), "r"(v) : "memory");
}

// ---------------- grid-wide barrier: per-block flags + aggregator ---------
__device__ __forceinline__ void grid_barrier(unsigned* localEpoch) {
    const unsigned e = *localEpoch + 1u;
    __syncthreads();
    if (threadIdx.x == 0)
        st_rel(&g_flags[blockIdx.x * 32], e);
    if (blockIdx.x == 0) {
        if (threadIdx.x < RGRID) {
            unsigned* f = &g_flags[threadIdx.x * 32];
            while ((int)(ld_acq(f) - e) < 0) { __nanosleep(32); }
        }
        __syncthreads();
        if (threadIdx.x == 0) st_rel(&g_barEpoch, e);
    } else {
        if (threadIdx.x == 0) {
            while ((int)(ld_acq(&g_barEpoch) - e) < 0) { __nanosleep(32); }
        }
        __syncthreads();
    }
    *localEpoch = e;
}

// ---------------- mma / ldmatrix / cp.async helpers ------------------------
__device__ __forceinline__ void ldsm4(unsigned& r0, unsigned& r1, unsigned& r2, unsigned& r3,
                                      const __half* p) {
    unsigned a = (unsigned)__cvta_generic_to_shared(p);
    asm volatile("ldmatrix.sync.aligned.m8n8.x4.shared.b16 {%0,%1,%2,%3}, [%4];"
                 : "=r"(r0), "=r"(r1), "=r"(r2), "=r"(r3) : "r"(a));
}
__device__ __forceinline__ void mma16816(float* d, const unsigned* a, unsigned b0, unsigned b1) {
    asm volatile("mma.sync.aligned.m16n8k16.row.col.f32.f16.f16.f32 "
                 "{%0,%1,%2,%3},{%4,%5,%6,%7},{%8,%9},{%0,%1,%2,%3};"
                 : "+f"(d[0]), "+f"(d[1]), "+f"(d[2]), "+f"(d[3])
                 : "r"(a[0]), "r"(a[1]), "r"(a[2]), "r"(a[3]), "r"(b0), "r"(b1));
}
__device__ __forceinline__ void cpa16(const __half* dst_smem, const __half* src) {
    unsigned a = (unsigned)__cvta_generic_to_shared(dst_smem);
    asm volatile("cp.async.cg.shared.global [%0], [%1], 16;" :: "r"(a), "l"(src));
}
__device__ __forceinline__ void cpa_commit() { asm volatile("cp.async.commit_group;"); }
__device__ __forceinline__ void cpa_wait0()  { asm volatile("cp.async.wait_group 0;"); }
__device__ __forceinline__ void cpa_wait1()  { asm volatile("cp.async.wait_group 1;"); }

// ---------------- embedding gather -> fp16 ----------------
__global__ void k_embed(const int* __restrict__ toks, const float* __restrict__ emb) {
    int idx = blockIdx.x * blockDim.x + threadIdx.x;      // float4 granularity
    const int total = BATCH*TT*(EE/4);
    if (idx >= total) return;
    int row = idx / (EE/4);
    int c   = idx - row*(EE/4);
    int tok = toks[row];
    float4 v = reinterpret_cast<const float4*>(emb + (size_t)tok*EE)[c];
    __half2* o = reinterpret_cast<__half2*>(g_xh) + (size_t)idx*2;
    o[0] = __floats2half2_rn(v.x, v.y);
    o[1] = __floats2half2_rn(v.z, v.w);
}

// ---------------- Wxh -> fp16 ----------------
__global__ void k_wx16(const float* __restrict__ Wxh) {
    int idx = blockIdx.x * blockDim.x + threadIdx.x;      // float4 granularity
    const int total = (2*2*GDIM*KINW)/4;
    if (idx >= total) return;
    float4 v = reinterpret_cast<const float4*>(Wxh)[idx];
    __half2* o = reinterpret_cast<__half2*>(g_wxh16) + (size_t)idx*2;
    o[0] = __floats2half2_rn(v.x, v.y);
    o[1] = __floats2half2_rn(v.z, v.w);
}

// ---------------- Whh -> fp16 gate-interleaved: [ld][j][kp][g] -------------
__global__ void k_wconv(const float* __restrict__ Whh) {
    int idx = blockIdx.x * blockDim.x + threadIdx.x;
    const int total = 2*2*1024*512;
    if (idx >= total) return;
    int kp = idx & 511;
    int j  = (idx >> 9) & 1023;
    int ld = idx >> 19;
    const float* Wl = Whh + (size_t)ld * GDIM * DD;
    __half2* outp = g_whhc + (size_t)idx * 4;
    #pragma unroll
    for (int g = 0; g < 4; ++g) {
        const float* wr = Wl + (size_t)(g*DD + j)*DD + 2*kp;
        outp[g] = __floats2half2_rn(wr[0], wr[1]);
    }
}

// ---------------- tensor-core GEMM: gx = x(fp16) . W(fp16)^T + bias --------
// C tile 128x128, K-chunk 32, double-buffered cp.async, 8 warps (4M x 2N),
// warp tile 32x64 = 2x8 m16n8k16 mmas per k16. Epilogue writes gate-interleaved.
#define GSTRIDE 40   // smem row stride in halves (80B: conflict-free ldmatrix)
__global__ __launch_bounds__(256) void k_gemm16(const float* __restrict__ bxh,
                                                const float* __restrict__ bhh,
                                                int layer) {
    const int d  = blockIdx.z;
    const int n0 = blockIdx.x * 128;
    const int m0 = blockIdx.y * 128;

    const __half* Bw = g_wxh16 + (size_t)(layer*2 + d) * GDIM * KINW;
    const float*  bx = bxh + (size_t)(layer*2 + d) * GDIM;
    const float*  bh = bhh + (size_t)(layer*2 + d) * GDIM;

    __shared__ __half As[2][128*GSTRIDE];
    __shared__ __half Bs[2][128*GSTRIDE];
    __shared__ float  sbias[128];

    const int tid  = threadIdx.x;
    const int warp = tid >> 5;
    const int lane = tid & 31;
    const int wm   = warp >> 1;        // 0..3
    const int wn   = warp & 1;         // 0..1

    const int bIdx  = m0 >> 12;        // 128-row tile never crosses batch
    const int sBase = m0 & (TT-1);

    if (tid < 128) sbias[tid] = bx[n0 + tid] + bh[n0 + tid];

    // per-thread load chunks: 512 16B-chunks per tile, 2 per thread
    const __half* aSrc[2];
    const __half* bSrc[2];
    int smemOff[2];
    #pragma unroll
    for (int i = 0; i < 2; ++i) {
        int c  = tid + i*256;
        int r  = c >> 2;               // tile row 0..127
        int kq = c & 3;                // 16B chunk within 32-half row
        int s    = sBase + r;
        int srow = d ? (TT-1-s) : s;
        aSrc[i] = g_xh + ((size_t)bIdx*TT + srow)*(size_t)KINW + kq*8;
        bSrc[i] = Bw   + (size_t)(n0 + r)*(size_t)KINW + kq*8;
        smemOff[i] = r*GSTRIDE + kq*8;
    }

    #define ISSUE(st) do { int _b = (st) & 1; size_t _k = (size_t)(st)*32;            \
        cpa16(&As[_b][smemOff[0]], aSrc[0] + _k); cpa16(&As[_b][smemOff[1]], aSrc[1] + _k); \
        cpa16(&Bs[_b][smemOff[0]], bSrc[0] + _k); cpa16(&Bs[_b][smemOff[1]], bSrc[1] + _k); \
        cpa_commit(); } while (0)

    float acc[2][8][4];
    #pragma unroll
    for (int mi=0;mi<2;mi++)
        #pragma unroll
        for (int ni=0;ni<8;ni++)
            #pragma unroll
            for (int q=0;q<4;q++) acc[mi][ni][q]=0.f;

    ISSUE(0);
    ISSUE(1);

    const int NSTAGE = KINW/32;   // 64
    for (int st = 0; st < NSTAGE; ++st) {
        if (st < NSTAGE-2) cpa_wait1(); else cpa_wait0();
        __syncthreads();

        const __half* Ab = As[st & 1];
        const __half* Bb = Bs[st & 1];
        #pragma unroll
        for (int ks = 0; ks < 2; ++ks) {
            unsigned af[2][4];
            #pragma unroll
            for (int mi = 0; mi < 2; ++mi) {
                int row = wm*32 + mi*16 + (lane & 7) + ((lane >> 3) & 1)*8;
                int col = ks*16 + (lane >> 4)*8;
                ldsm4(af[mi][0], af[mi][1], af[mi][2], af[mi][3], Ab + row*GSTRIDE + col);
            }
            unsigned bf[4][4];
            #pragma unroll
            for (int nj = 0; nj < 4; ++nj) {
                int g    = lane >> 3;
                int brow = wn*64 + nj*16 + (lane & 7) + ((g >> 1) & 1)*8;
                int bcol = ks*16 + (g & 1)*8;
                ldsm4(bf[nj][0], bf[nj][1], bf[nj][2], bf[nj][3], Bb + brow*GSTRIDE + bcol);
            }
            #pragma unroll
            for (int mi = 0; mi < 2; ++mi)
                #pragma unroll
                for (int ni = 0; ni < 8; ++ni)
                    mma16816(acc[mi][ni], af[mi],
                             bf[ni>>1][(ni&1)*2], bf[ni>>1][(ni&1)*2+1]);
        }
        __syncthreads();
        if (st + 2 < NSTAGE) ISSUE(st + 2);
    }
    #undef ISSUE

    // epilogue: gate-interleaved store  addr = row*4096 + j*4 + gate
    #pragma unroll
    for (int mi = 0; mi < 2; ++mi) {
        int lrowBase = wm*32 + mi*16 + (lane >> 2);
        #pragma unroll
        for (int hf = 0; hf < 2; ++hf) {
            int lrow = lrowBase + hf*8;
            size_t rowbase = ((size_t)(d*BATCH + bIdx)*TT + sBase + lrow)*(size_t)GDIM;
            #pragma unroll
            for (int ni = 0; ni < 8; ++ni) {
                int lcol = wn*64 + ni*8 + (lane & 3)*2;
                float v0 = acc[mi][ni][hf*2+0] + sbias[lcol];
                float v1 = acc[mi][ni][hf*2+1] + sbias[lcol+1];
                int gn0 = n0 + lcol, gn1 = gn0 + 1;
                g_gx[rowbase + (size_t)(gn0 & 1023)*4 + (gn0 >> 10)] = v0;
                g_gx[rowbase + (size_t)(gn1 & 1023)*4 + (gn1 >> 10)] = v1;
            }
        }
    }
}

// ---------------- persistent biLSTM recurrence over T steps ----------------
__global__ __launch_bounds__(RTHREADS) void k_recur(int layer) {
    __shared__ float h_sm[2*BATCH*DD];
    const int tid  = threadIdx.x;
    const int warp = tid >> 5;
    const int lane = tid & 31;

    unsigned int localEpoch = ld_acq(&g_barEpoch);

    for (int i = blockIdx.x*RTHREADS + tid; i < 2*BATCH*DD; i += RGRID*RTHREADS)
        g_hcur[0][i] = 0.f;
    grid_barrier(&localEpoch);

    const int u0 = blockIdx.x * UPB;
    int nLocal = NUNITS - u0;
    if (nLocal > UPB) nLocal = UPB;
    if (nLocal < 0)   nLocal = 0;

    int stage_base = 0, stage_q = 0;
    if (nLocal > 0) {
        int d_lo = u0 >> 10;
        int d_hi = (u0 + nLocal - 1) >> 10;
        stage_base = d_lo * (BATCH*DD/4);
        stage_q    = (d_hi - d_lo + 1) * (BATCH*DD/4);
    }

    const uint4* wq[2];
    const float2* hp2[2];
    int jj[2], dd_[2], valid[2];
    #pragma unroll
    for (int r=0;r<2;r++) {
        int lu = warp + 8*r;
        valid[r] = (lu < nLocal);
        int u = u0 + (valid[r] ? lu : 0);
        if (u >= NUNITS) u = 0;
        int d = u >> 10;
        int j = u & (DD-1);
        dd_[r] = d; jj[r] = j;
        wq[r]  = reinterpret_cast<const uint4*>(
                     g_whhc + ((size_t)((layer*2 + d)*1024 + j) * 512) * 4);
        hp2[r] = reinterpret_cast<const float2*>(h_sm + d*BATCH*DD);
    }
    float creg[2] = {0.f, 0.f};
    const float4* gx4 = reinterpret_cast<const float4*>(g_gx);

    for (int t = 0; t < TT; ++t) {
        const int rb = t & 1;
        const int wb = rb ^ 1;

        float4 pre[2];
        #pragma unroll
        for (int r=0;r<2;r++)
            if (lane < BATCH)
                pre[r] = __ldcg(gx4 + ((size_t)(dd_[r]*BATCH + lane)*TT + t)*DD + jj[r]);

        {
            const float4* src = reinterpret_cast<const float4*>(g_hcur[rb]) + stage_base;
            float4* dst = reinterpret_cast<float4*>(h_sm) + stage_base;
            for (int i = tid; i < stage_q; i += RTHREADS)
                dst[i] = __ldcg(src + i);
        }
        __syncthreads();

        #pragma unroll
        for (int r = 0; r < 2; ++r) {
            if (!valid[r]) continue;
            const uint4* w = wq[r];
            const float2* hp = hp2[r];

            float2 acc2[4][4];
            #pragma unroll
            for (int g=0;g<4;g++)
                #pragma unroll
                for (int b=0;b<4;b++) acc2[g][b] = make_float2(0.f, 0.f);

            #pragma unroll
            for (int it = 0; it < 16; ++it) {
                int kp = it*32 + lane;
                uint4 wv = w[kp];
                float2 w0 = __half22float2(*reinterpret_cast<__half2*>(&wv.x));
                float2 w1 = __half22float2(*reinterpret_cast<__half2*>(&wv.y));
                float2 w2 = __half22float2(*reinterpret_cast<__half2*>(&wv.z));
                float2 w3 = __half22float2(*reinterpret_cast<__half2*>(&wv.w));
                float2 h0 = hp[0*512 + kp];
                float2 h1 = hp[1*512 + kp];
                float2 h2 = hp[2*512 + kp];
                float2 h3 = hp[3*512 + kp];
                fma2f(acc2[0][0], w0, h0); fma2f(acc2[0][1], w0, h1);
                fma2f(acc2[0][2], w0, h2); fma2f(acc2[0][3], w0, h3);
                fma2f(acc2[1][0], w1, h0); fma2f(acc2[1][1], w1, h1);
                fma2f(acc2[1][2], w1, h2); fma2f(acc2[1][3], w1, h3);
                fma2f(acc2[2][0], w2, h0); fma2f(acc2[2][1], w2, h1);
                fma2f(acc2[2][2], w2, h2); fma2f(acc2[2][3], w2, h3);
                fma2f(acc2[3][0], w3, h0); fma2f(acc2[3][1], w3, h1);
                fma2f(acc2[3][2], w3, h2); fma2f(acc2[3][3], w3, h3);
            }

            float acc[4][4];
            #pragma unroll
            for (int g=0;g<4;g++)
                #pragma unroll
                for (int b=0;b<4;b++) {
                    float s = acc2[g][b].x + acc2[g][b].y;
                    #pragma unroll
                    for (int off=16; off>0; off>>=1)
                        s += __shfl_xor_sync(0xffffffffu, s, off);
                    acc[g][b] = s;
                }

            const int d = dd_[r];
            const int j = jj[r];
            if (lane < BATCH) {
                const int bb = lane;
                float pi = acc[0][bb] + pre[r].x;
                float pg = acc[1][bb] + pre[r].y;
                float pf = acc[2][bb] + pre[r].z;
                float po = acc[3][bb] + pre[r].w;
                float ii = 1.f/(1.f + expf(-pi));
                float gg = tanhf(pg);
                float ff = 1.f/(1.f + expf(-pf));
                float oo = 1.f/(1.f + expf(-po));
                float c  = ff*creg[r] + ii*gg;
                creg[r]  = c;
                float h  = oo * tanhf(c);
                g_hcur[wb][(d*BATCH + bb)*DD + j] = h;
                float* hist = (d == 0) ? g_hL : g_hR;
                hist[((size_t)bb*TT + t)*DD + j] = h;
            }
        }
        grid_barrier(&localEpoch);
    }
}

// ---------------- layer-1 input: x[b][t] = [hL[b][t], hR[b][T-1-t]] (fp16) -
__global__ void k_concat() {
    int idx = blockIdx.x * blockDim.x + threadIdx.x;    // float4 granularity
    const int total = BATCH*TT*(KINW/4);
    if (idx >= total) return;
    int c   = idx & (KINW/4 - 1);
    int row = idx >> 9;
    int b   = row >> 12;
    int t   = row & (TT-1);
    float4 v;
    if (c < DD/4) {
        v = reinterpret_cast<const float4*>(g_hL + ((size_t)b*TT + t)*DD)[c];
    } else {
        v = reinterpret_cast<const float4*>(g_hR + ((size_t)b*TT + (TT-1-t))*DD)[c - DD/4];
    }
    __half2* o = reinterpret_cast<__half2*>(g_xh) + (size_t)idx*2;
    o[0] = __floats2half2_rn(v.x, v.y);
    o[1] = __floats2half2_rn(v.z, v.w);
}

// ---------------- attention logits -----------------------------------------
__global__ void k_dots() {
    const int b = blockIdx.x >> 12;
    const int t = blockIdx.x & (TT-1);
    const int tid = threadIdx.x;
    const float* hl  = g_hL + ((size_t)b*TT + t)*DD;
    const float* hll = g_hL + ((size_t)b*TT + (TT-1))*DD;
    const float* hr  = g_hR + ((size_t)b*TT + t)*DD;
    const float* hrl = g_hR + ((size_t)b*TT + (TT-1))*DD;
    float s = 0.f;
    for (int j = tid; j < DD; j += 256)
        s += hl[j]*hll[j] + hr[j]*hrl[j];
    #pragma unroll
    for (int o=16;o>0;o>>=1) s += __shfl_xor_sync(0xffffffffu, s, o);
    __shared__ float red[8];
    if ((tid & 31) == 0) red[tid>>5] = s;
    __syncthreads();
    if (tid == 0) {
        float v = 0.f;
        #pragma unroll
        for (int w=0;w<8;w++) v += red[w];
        g_wv[(size_t)b*TT + t] = v * (1.f/64.f);   // 1/sqrt(4096)
    }
}

// ---------------- softmax per batch -----------------------------------------
__global__ void k_softmax() {
    const int b = blockIdx.x, tid = threadIdx.x;   // 1024 threads
    __shared__ float red[32];
    __shared__ float sval;
    const float* w = g_wv + (size_t)b*TT;
    float m = -1e30f;
    for (int t = tid; t < TT; t += 1024) m = fmaxf(m, w[t]);
    #pragma unroll
    for (int o=16;o>0;o>>=1) m = fmaxf(m, __shfl_xor_sync(0xffffffffu, m, o));
    if ((tid&31)==0) red[tid>>5] = m;
    __syncthreads();
    if (tid < 32) {
        float v = red[tid];
        #pragma unroll
        for (int o=16;o>0;o>>=1) v = fmaxf(v, __shfl_xor_sync(0xffffffffu, v, o));
        if (tid==0) sval = v;
    }
    __syncthreads();
    m = sval;
    float s = 0.f;
    for (int t = tid; t < TT; t += 1024) {
        float e = expf(w[t] - m);
        g_att[(size_t)b*TT + t] = e;
        s += e;
    }
    #pragma unroll
    for (int o=16;o>0;o>>=1) s += __shfl_xor_sync(0xffffffffu, s, o);
    __syncthreads();
    if ((tid&31)==0) red[tid>>5] = s;
    __syncthreads();
    if (tid < 32) {
        float v = red[tid];
        #pragma unroll
        for (int o=16;o>0;o>>=1) v += __shfl_xor_sync(0xffffffffu, v, o);
        if (tid==0) sval = v;
    }
    __syncthreads();
    float inv = 1.f / sval;
    for (int t = tid; t < TT; t += 1024)
        g_att[(size_t)b*TT + t] *= inv;
}

// ---------------- context vectors -------------------------------------------
__global__ void k_ctxt() {
    const int b = blockIdx.y;
    const int j = blockIdx.x*128 + threadIdx.x;
    const float* att = g_att + (size_t)b*TT;
    float aL = 0.f, aR = 0.f;
    for (int t = 0; t < TT; t += 4) {
        float a0 = att[t], a1 = att[t+1], a2 = att[t+2], a3 = att[t+3];
        const float* hl = g_hL + ((size_t)b*TT + t)*DD + j;
        const float* hr = g_hR + ((size_t)b*TT + t)*DD + j;
        aL += a0*hl[0] + a1*hl[DD] + a2*hl[2*DD] + a3*hl[3*DD];
        aR += a0*hr[0] + a1*hr[DD] + a2*hr[2*DD] + a3*hr[3*DD];
    }
    g_ctxtL[b*DD + j] = aL;
    g_ctxtR[b*DD + j] = aR;
}

// ---------------- output ----------------------------------------------------
__global__ void k_out(const float* __restrict__ WcyL, const float* __restrict__ WcyR,
                      float* __restrict__ out) {
    const int b = blockIdx.x;
    const int m = threadIdx.x >> 5;
    const int lane = threadIdx.x & 31;
    float s = 0.f;
    for (int j = lane; j < DD; j += 32)
        s += WcyL[m*DD + j]*g_ctxtL[b*DD + j] + WcyR[m*DD + j]*g_ctxtR[b*DD + j];
    #pragma unroll
    for (int o=16;o>0;o>>=1) s += __shfl_xor_sync(0xffffffffu, s, o);
    if (lane == 0) out[b*MOUT + m] = s;
}

// ---------------- launcher ---------------------------------------------------
extern "C" void kernel_launch(void* const* d_in, const int* in_sizes, int n_in,
                              void* d_out, int out_size) {
    const int*   toks = (const int*)  d_in[0];
    const float* emb  = (const float*)d_in[1];
    const float* Wxh  = (const float*)d_in[2];
    const float* Whh  = (const float*)d_in[3];
    const float* bxh  = (const float*)d_in[4];
    const float* bhh  = (const float*)d_in[5];
    const float* WcyL = (const float*)d_in[6];
    const float* WcyR = (const float*)d_in[7];
    float* out = (float*)d_out;
    (void)in_sizes; (void)n_in; (void)out_size;

    k_embed<<<(BATCH*TT*(EE/4) + 255)/256, 256>>>(toks, emb);
    k_wconv<<<(2*2*1024*512 + 255)/256, 256>>>(Whh);
    k_wx16<<<((2*2*GDIM*KINW)/4 + 255)/256, 256>>>(Wxh);

    for (int layer = 0; layer < 2; ++layer) {
        dim3 ggrid(GDIM/128, (BATCH*TT)/128, 2);
        k_gemm16<<<ggrid, 256>>>(bxh, bhh, layer);
        k_recur<<<RGRID, RTHREADS>>>(layer);
        if (layer == 0)
            k_concat<<<(BATCH*TT*(KINW/4) + 255)/256, 256>>>();
    }

    k_dots<<<BATCH*TT, 256>>>();
    k_softmax<<<BATCH, 1024>>>();
    dim3 cgrid(DD/128, BATCH);
    k_ctxt<<<cgrid, 128>>>();
    k_out<<<BATCH, 64>>>(WcyL, WcyR, out);
}

// round 13
// speedup vs baseline: 1.5674x; 1.2183x over previous
#include <cuda_runtime.h>
#include <cuda_fp16.h>
#include <math.h>

// Problem constants
#define BATCH   4
#define TT      4096
#define EE      2048
#define DD      1024
#define GDIM    4096          // 4*DD gate rows
#define MOUT    2
#define KINW    2048          // input width per layer (E for l0, 2*DD for l1)

// Recurrence persistent-kernel config
#define RGRID    148
#define RTHREADS 256
#define NBD      74           // blocks per direction
#define UPB      14           // units per block (74*14 = 1036 >= 1024)

// Recurrence smem layout (dynamic)
#define SMEM_WA_H  (64*1032)          // A: 64 rows x 1032 halves (1024 + 8 pad)
#define SMEM_HB_H  (1024*8)           // B: 1024 k x 8 n halves
#define SMEM_REC_BYTES (SMEM_WA_H*2 + SMEM_HB_H*2 + 64*8*4)

// ---------------- scratch (static device arrays only; no allocation) ------
__device__ __align__(128) __half  g_xh  [BATCH*TT*KINW];      // fp16 layer input
__device__ __align__(128) __half  g_wxh16[2u*2u*GDIM*KINW];   // fp16 Wxh
__device__ __align__(128) __half  g_whh16r[2u*2u*GDIM*DD];    // fp16 Whh rows = j*4+g
__device__ __align__(128) float g_gx  [2u*BATCH*TT*GDIM];     // preacts [d][b][t][j][gate]
__device__ __align__(128) float g_hL  [BATCH*TT*DD];
__device__ __align__(128) float g_hR  [BATCH*TT*DD];
__device__ __align__(128) float g_hcur[2][2*BATCH*DD];
__device__ __align__(128) unsigned g_flags[RGRID*32];
__device__ __align__(128) unsigned g_barE[2*32];              // per-dir epoch
__device__ float g_wv  [BATCH*TT];
__device__ float g_att [BATCH*TT];
__device__ float g_ctxtL[BATCH*DD];
__device__ float g_ctxtR[BATCH*DD];

// ---------------- scoped release/acquire primitives -----------------------
__device__ __forceinline__ unsigned ld_acq(unsigned* p) {
    unsigned v; asm volatile("ld.acquire.gpu.u32 %0, [%1];" : "=r"(v) : "l"(p) : "memory"); return v;
}
__device__ __forceinline__ void st_rel(unsigned* p, unsigned v) {
    asm volatile("st.release.gpu.u32 [%0], %1;" :: "l"(p), "r"(v) : "memory");
}

// ---------------- per-direction grid barrier (74 blocks) -------------------
__device__ __forceinline__ void grid_barrier_dir(int d, int blk, unsigned* le) {
    const unsigned e = *le + 1u;
    __syncthreads();
    if (threadIdx.x == 0)
        st_rel(&g_flags[(d*NBD + blk)*32], e);
    if (blk == 0) {
        if (threadIdx.x < NBD) {
            unsigned* f = &g_flags[(d*NBD + threadIdx.x)*32];
            while ((int)(ld_acq(f) - e) < 0) {}
        }
        __syncthreads();
        if (threadIdx.x == 0) st_rel(&g_barE[d*32], e);
    } else {
        if (threadIdx.x == 0) {
            while ((int)(ld_acq(&g_barE[d*32]) - e) < 0) {}
        }
        __syncthreads();
    }
    *le = e;
}

// ---------------- mma / ldmatrix / cp.async helpers ------------------------
__device__ __forceinline__ void ldsm4(unsigned& r0, unsigned& r1, unsigned& r2, unsigned& r3,
                                      const __half* p) {
    unsigned a = (unsigned)__cvta_generic_to_shared(p);
    asm volatile("ldmatrix.sync.aligned.m8n8.x4.shared.b16 {%0,%1,%2,%3}, [%4];"
                 : "=r"(r0), "=r"(r1), "=r"(r2), "=r"(r3) : "r"(a));
}
__device__ __forceinline__ void ldsm2t(unsigned& r0, unsigned& r1, const __half* p) {
    unsigned a = (unsigned)__cvta_generic_to_shared(p);
    asm volatile("ldmatrix.sync.aligned.m8n8.x2.trans.shared.b16 {%0,%1}, [%2];"
                 : "=r"(r0), "=r"(r1) : "r"(a));
}
__device__ __forceinline__ void mma16816(float* d, const unsigned* a, unsigned b0, unsigned b1) {
    asm volatile("mma.sync.aligned.m16n8k16.row.col.f32.f16.f16.f32 "
                 "{%0,%1,%2,%3},{%4,%5,%6,%7},{%8,%9},{%0,%1,%2,%3};"
                 : "+f"(d[0]), "+f"(d[1]), "+f"(d[2]), "+f"(d[3])
                 : "r"(a[0]), "r"(a[1]), "r"(a[2]), "r"(a[3]), "r"(b0), "r"(b1));
}
__device__ __forceinline__ void mma16816v(float* d, unsigned a0, unsigned a1, unsigned a2,
                                          unsigned a3, unsigned b0, unsigned b1) {
    asm volatile("mma.sync.aligned.m16n8k16.row.col.f32.f16.f16.f32 "
                 "{%0,%1,%2,%3},{%4,%5,%6,%7},{%8,%9},{%0,%1,%2,%3};"
                 : "+f"(d[0]), "+f"(d[1]), "+f"(d[2]), "+f"(d[3])
                 : "r"(a0), "r"(a1), "r"(a2), "r"(a3), "r"(b0), "r"(b1));
}
__device__ __forceinline__ void cpa16(const __half* dst_smem, const __half* src) {
    unsigned a = (unsigned)__cvta_generic_to_shared(dst_smem);
    asm volatile("cp.async.cg.shared.global [%0], [%1], 16;" :: "r"(a), "l"(src));
}
__device__ __forceinline__ void cpa_commit() { asm volatile("cp.async.commit_group;"); }
__device__ __forceinline__ void cpa_wait0()  { asm volatile("cp.async.wait_group 0;"); }
__device__ __forceinline__ void cpa_wait1()  { asm volatile("cp.async.wait_group 1;"); }

// ---------------- embedding gather -> fp16 ----------------
__global__ void k_embed(const int* __restrict__ toks, const float* __restrict__ emb) {
    int idx = blockIdx.x * blockDim.x + threadIdx.x;      // float4 granularity
    const int total = BATCH*TT*(EE/4);
    if (idx >= total) return;
    int row = idx / (EE/4);
    int c   = idx - row*(EE/4);
    int tok = toks[row];
    float4 v = reinterpret_cast<const float4*>(emb + (size_t)tok*EE)[c];
    __half2* o = reinterpret_cast<__half2*>(g_xh) + (size_t)idx*2;
    o[0] = __floats2half2_rn(v.x, v.y);
    o[1] = __floats2half2_rn(v.z, v.w);
}

// ---------------- Wxh -> fp16 ----------------
__global__ void k_wx16(const float* __restrict__ Wxh) {
    int idx = blockIdx.x * blockDim.x + threadIdx.x;      // float4 granularity
    const int total = (2*2*GDIM*KINW)/4;
    if (idx >= total) return;
    float4 v = reinterpret_cast<const float4*>(Wxh)[idx];
    __half2* o = reinterpret_cast<__half2*>(g_wxh16) + (size_t)idx*2;
    o[0] = __floats2half2_rn(v.x, v.y);
    o[1] = __floats2half2_rn(v.z, v.w);
}

// ---------------- Whh -> fp16, row-reordered: [ld][j*4+g][k] ---------------
__global__ void k_whhr(const float* __restrict__ Whh) {
    int idx = blockIdx.x * blockDim.x + threadIdx.x;      // half2 granularity
    const int total = 2*2*4096*512;
    if (idx >= total) return;
    int k2  = idx & 511;
    int row = (idx >> 9) & 4095;        // j*4 + g
    int ld  = idx >> 21;
    int j = row >> 2, g = row & 3;
    const float* src = Whh + ((size_t)ld*4096 + g*1024 + j)*1024 + k2*2;
    reinterpret_cast<__half2*>(g_whh16r)[idx] = __floats2half2_rn(src[0], src[1]);
}

// ---------------- tensor-core GEMM: gx = x(fp16) . W(fp16)^T + bias --------
#define GSTRIDE 40   // smem row stride in halves
__global__ __launch_bounds__(256) void k_gemm16(const float* __restrict__ bxh,
                                                const float* __restrict__ bhh,
                                                int layer) {
    const int d  = blockIdx.z;
    const int n0 = blockIdx.x * 128;
    const int m0 = blockIdx.y * 128;

    const __half* Bw = g_wxh16 + (size_t)(layer*2 + d) * GDIM * KINW;
    const float*  bx = bxh + (size_t)(layer*2 + d) * GDIM;
    const float*  bh = bhh + (size_t)(layer*2 + d) * GDIM;

    __shared__ __half As[2][128*GSTRIDE];
    __shared__ __half Bs[2][128*GSTRIDE];
    __shared__ float  sbias[128];

    const int tid  = threadIdx.x;
    const int warp = tid >> 5;
    const int lane = tid & 31;
    const int wm   = warp >> 1;
    const int wn   = warp & 1;

    const int bIdx  = m0 >> 12;
    const int sBase = m0 & (TT-1);

    if (tid < 128) sbias[tid] = bx[n0 + tid] + bh[n0 + tid];

    const __half* aSrc[2];
    const __half* bSrc[2];
    int smemOff[2];
    #pragma unroll
    for (int i = 0; i < 2; ++i) {
        int c  = tid + i*256;
        int r  = c >> 2;
        int kq = c & 3;
        int s    = sBase + r;
        int srow = d ? (TT-1-s) : s;
        aSrc[i] = g_xh + ((size_t)bIdx*TT + srow)*(size_t)KINW + kq*8;
        bSrc[i] = Bw   + (size_t)(n0 + r)*(size_t)KINW + kq*8;
        smemOff[i] = r*GSTRIDE + kq*8;
    }

    #define ISSUE(st) do { int _b = (st) & 1; size_t _k = (size_t)(st)*32;            \
        cpa16(&As[_b][smemOff[0]], aSrc[0] + _k); cpa16(&As[_b][smemOff[1]], aSrc[1] + _k); \
        cpa16(&Bs[_b][smemOff[0]], bSrc[0] + _k); cpa16(&Bs[_b][smemOff[1]], bSrc[1] + _k); \
        cpa_commit(); } while (0)

    float acc[2][8][4];
    #pragma unroll
    for (int mi=0;mi<2;mi++)
        #pragma unroll
        for (int ni=0;ni<8;ni++)
            #pragma unroll
            for (int q=0;q<4;q++) acc[mi][ni][q]=0.f;

    ISSUE(0);
    ISSUE(1);

    const int NSTAGE = KINW/32;   // 64
    for (int st = 0; st < NSTAGE; ++st) {
        if (st < NSTAGE-2) cpa_wait1(); else cpa_wait0();
        __syncthreads();

        const __half* Ab = As[st & 1];
        const __half* Bb = Bs[st & 1];
        #pragma unroll
        for (int ks = 0; ks < 2; ++ks) {
            unsigned af[2][4];
            #pragma unroll
            for (int mi = 0; mi < 2; ++mi) {
                int row = wm*32 + mi*16 + (lane & 7) + ((lane >> 3) & 1)*8;
                int col = ks*16 + (lane >> 4)*8;
                ldsm4(af[mi][0], af[mi][1], af[mi][2], af[mi][3], Ab + row*GSTRIDE + col);
            }
            unsigned bf[4][4];
            #pragma unroll
            for (int nj = 0; nj < 4; ++nj) {
                int g    = lane >> 3;
                int brow = wn*64 + nj*16 + (lane & 7) + ((g >> 1) & 1)*8;
                int bcol = ks*16 + (g & 1)*8;
                ldsm4(bf[nj][0], bf[nj][1], bf[nj][2], bf[nj][3], Bb + brow*GSTRIDE + bcol);
            }
            #pragma unroll
            for (int mi = 0; mi < 2; ++mi)
                #pragma unroll
                for (int ni = 0; ni < 8; ++ni)
                    mma16816(acc[mi][ni], af[mi],
                             bf[ni>>1][(ni&1)*2], bf[ni>>1][(ni&1)*2+1]);
        }
        __syncthreads();
        if (st + 2 < NSTAGE) ISSUE(st + 2);
    }
    #undef ISSUE

    #pragma unroll
    for (int mi = 0; mi < 2; ++mi) {
        int lrowBase = wm*32 + mi*16 + (lane >> 2);
        #pragma unroll
        for (int hf = 0; hf < 2; ++hf) {
            int lrow = lrowBase + hf*8;
            size_t rowbase = ((size_t)(d*BATCH + bIdx)*TT + sBase + lrow)*(size_t)GDIM;
            #pragma unroll
            for (int ni = 0; ni < 8; ++ni) {
                int lcol = wn*64 + ni*8 + (lane & 3)*2;
                float v0 = acc[mi][ni][hf*2+0] + sbias[lcol];
                float v1 = acc[mi][ni][hf*2+1] + sbias[lcol+1];
                int gn0 = n0 + lcol, gn1 = gn0 + 1;
                g_gx[rowbase + (size_t)(gn0 & 1023)*4 + (gn0 >> 10)] = v0;
                g_gx[rowbase + (size_t)(gn1 & 1023)*4 + (gn1 >> 10)] = v1;
            }
        }
    }
}

// ---------------- persistent biLSTM recurrence: tensor-core matvec ---------
// Block owns up to 14 units of ONE direction. A = Whh rows [unit*4+gate] in
// smem (loaded once, 128KB). Per step: stage h -> fp16 [k][8], 4 warps do
// m16n8k16 over K=1024 (C = 64x8), epilogue does gates+state for 56 (unit,b).
__global__ __launch_bounds__(RTHREADS) void k_recur(int layer) {
    extern __shared__ char rsm[];
    __half* WA  = reinterpret_cast<__half*>(rsm);
    __half* HB  = reinterpret_cast<__half*>(rsm + SMEM_WA_H*2);
    float*  Csm = reinterpret_cast<float*> (rsm + SMEM_WA_H*2 + SMEM_HB_H*2);

    const int tid  = threadIdx.x;
    const int warp = tid >> 5;
    const int lane = tid & 31;
    const int d    = (blockIdx.x >= NBD) ? 1 : 0;
    const int blk  = blockIdx.x - d*NBD;
    const int base = blk * UPB;
    const int nU   = (DD - base < UPB) ? (DD - base) : UPB;   // 2..14
    const int nRows = nU * 4;

    // load recurrent weights into smem A (once), zero-pad rows to 64
    {
        const __half* Wsrc = g_whh16r + ((size_t)(layer*2 + d)*4096 + (size_t)base*4) * DD;
        for (int c = tid; c < 64*128; c += RTHREADS) {      // 16B chunks
            int row = c >> 7, q = c & 127;
            uint4 v = make_uint4(0u,0u,0u,0u);
            if (row < nRows)
                v = *(reinterpret_cast<const uint4*>(Wsrc + (size_t)row*DD) + q);
            *reinterpret_cast<uint4*>(WA + row*1032 + q*8) = v;
        }
    }

    unsigned localEpoch = ld_acq(&g_barE[d*32]);
    // zero h buffer 0 for this direction
    for (int i = tid; i < 4*DD; i += RTHREADS)
        g_hcur[0][d*4*DD + i] = 0.f;
    grid_barrier_dir(d, blk, &localEpoch);

    const int lu = tid >> 2, bb = tid & 3;
    const bool fin = (tid < nRows);
    float creg = 0.f;
    const float4* gx4 = reinterpret_cast<const float4*>(g_gx);
    float* hist = d ? g_hR : g_hL;

    // per-warp static ldmatrix bases
    const __half* Abase = WA + (size_t)((warp & 3)*16 + (lane & 7) + ((lane >> 3) & 1)*8) * 1032
                             + (lane >> 4)*8;
    const __half* Bbase = HB + (size_t)(lane & 15)*8;

    for (int t = 0; t < TT; ++t) {
        const int rb = t & 1, wb = rb ^ 1;

        float4 pre = make_float4(0.f,0.f,0.f,0.f);
        if (fin)
            pre = __ldcg(gx4 + ((size_t)(d*BATCH + bb)*TT + t)*DD + (base + lu));

        // stage h -> HB[k][8] fp16 (cols 4-7 zero)
        #pragma unroll
        for (int i = 0; i < 4; ++i) {
            int k = tid + i*256;
            float v0 = __ldcg(&g_hcur[rb][(d*4+0)*DD + k]);
            float v1 = __ldcg(&g_hcur[rb][(d*4+1)*DD + k]);
            float v2 = __ldcg(&g_hcur[rb][(d*4+2)*DD + k]);
            float v3 = __ldcg(&g_hcur[rb][(d*4+3)*DD + k]);
            __half2 p0 = __floats2half2_rn(v0, v1);
            __half2 p1 = __floats2half2_rn(v2, v3);
            uint4 pk;
            pk.x = *reinterpret_cast<unsigned*>(&p0);
            pk.y = *reinterpret_cast<unsigned*>(&p1);
            pk.z = 0u; pk.w = 0u;
            *reinterpret_cast<uint4*>(HB + k*8) = pk;
        }
        __syncthreads();

        if (warp < 4) {
            float cacc[4] = {0.f, 0.f, 0.f, 0.f};
            #pragma unroll
            for (int ks = 0; ks < 64; ++ks) {
                unsigned a0,a1,a2,a3,b0,b1;
                ldsm4(a0, a1, a2, a3, Abase + ks*16);
                ldsm2t(b0, b1, Bbase + (size_t)ks*16*8);
                mma16816v(cacc, a0, a1, a2, a3, b0, b1);
            }
            int r  = warp*16 + (lane >> 2);
            int cc = (lane & 3)*2;
            *reinterpret_cast<float2*>(&Csm[r*8 + cc])     = make_float2(cacc[0], cacc[1]);
            *reinterpret_cast<float2*>(&Csm[(r+8)*8 + cc]) = make_float2(cacc[2], cacc[3]);
        }
        __syncthreads();

        if (fin) {
            float pi = Csm[(lu*4+0)*8 + bb] + pre.x;
            float pg = Csm[(lu*4+1)*8 + bb] + pre.y;
            float pf = Csm[(lu*4+2)*8 + bb] + pre.z;
            float po = Csm[(lu*4+3)*8 + bb] + pre.w;
            float ii = 1.f/(1.f + __expf(-pi));
            float gg = 2.f/(1.f + __expf(-2.f*pg)) - 1.f;
            float ff = 1.f/(1.f + __expf(-pf));
            float oo = 1.f/(1.f + __expf(-po));
            float c  = ff*creg + ii*gg;
            creg = c;
            float th = 2.f/(1.f + __expf(-2.f*c)) - 1.f;
            float h  = oo * th;
            g_hcur[wb][(d*4 + bb)*DD + base + lu] = h;
            hist[((size_t)bb*TT + t)*DD + base + lu] = h;
        }
        grid_barrier_dir(d, blk, &localEpoch);
    }
}

// ---------------- layer-1 input: x[b][t] = [hL[b][t], hR[b][T-1-t]] (fp16) -
__global__ void k_concat() {
    int idx = blockIdx.x * blockDim.x + threadIdx.x;    // float4 granularity
    const int total = BATCH*TT*(KINW/4);
    if (idx >= total) return;
    int c   = idx & (KINW/4 - 1);
    int row = idx >> 9;
    int b   = row >> 12;
    int t   = row & (TT-1);
    float4 v;
    if (c < DD/4) {
        v = reinterpret_cast<const float4*>(g_hL + ((size_t)b*TT + t)*DD)[c];
    } else {
        v = reinterpret_cast<const float4*>(g_hR + ((size_t)b*TT + (TT-1-t))*DD)[c - DD/4];
    }
    __half2* o = reinterpret_cast<__half2*>(g_xh) + (size_t)idx*2;
    o[0] = __floats2half2_rn(v.x, v.y);
    o[1] = __floats2half2_rn(v.z, v.w);
}

// ---------------- attention logits -----------------------------------------
__global__ void k_dots() {
    const int b = blockIdx.x >> 12;
    const int t = blockIdx.x & (TT-1);
    const int tid = threadIdx.x;
    const float* hl  = g_hL + ((size_t)b*TT + t)*DD;
    const float* hll = g_hL + ((size_t)b*TT + (TT-1))*DD;
    const float* hr  = g_hR + ((size_t)b*TT + t)*DD;
    const float* hrl = g_hR + ((size_t)b*TT + (TT-1))*DD;
    float s = 0.f;
    for (int j = tid; j < DD; j += 256)
        s += hl[j]*hll[j] + hr[j]*hrl[j];
    #pragma unroll
    for (int o=16;o>0;o>>=1) s += __shfl_xor_sync(0xffffffffu, s, o);
    __shared__ float red[8];
    if ((tid & 31) == 0) red[tid>>5] = s;
    __syncthreads();
    if (tid == 0) {
        float v = 0.f;
        #pragma unroll
        for (int w=0;w<8;w++) v += red[w];
        g_wv[(size_t)b*TT + t] = v * (1.f/64.f);   // 1/sqrt(4096)
    }
}

// ---------------- softmax per batch -----------------------------------------
__global__ void k_softmax() {
    const int b = blockIdx.x, tid = threadIdx.x;   // 1024 threads
    __shared__ float red[32];
    __shared__ float sval;
    const float* w = g_wv + (size_t)b*TT;
    float m = -1e30f;
    for (int t = tid; t < TT; t += 1024) m = fmaxf(m, w[t]);
    #pragma unroll
    for (int o=16;o>0;o>>=1) m = fmaxf(m, __shfl_xor_sync(0xffffffffu, m, o));
    if ((tid&31)==0) red[tid>>5] = m;
    __syncthreads();
    if (tid < 32) {
        float v = red[tid];
        #pragma unroll
        for (int o=16;o>0;o>>=1) v = fmaxf(v, __shfl_xor_sync(0xffffffffu, v, o));
        if (tid==0) sval = v;
    }
    __syncthreads();
    m = sval;
    float s = 0.f;
    for (int t = tid; t < TT; t += 1024) {
        float e = expf(w[t] - m);
        g_att[(size_t)b*TT + t] = e;
        s += e;
    }
    #pragma unroll
    for (int o=16;o>0;o>>=1) s += __shfl_xor_sync(0xffffffffu, s, o);
    __syncthreads();
    if ((tid&31)==0) red[tid>>5] = s;
    __syncthreads();
    if (tid < 32) {
        float v = red[tid];
        #pragma unroll
        for (int o=16;o>0;o>>=1) v += __shfl_xor_sync(0xffffffffu, v, o);
        if (tid==0) sval = v;
    }
    __syncthreads();
    float inv = 1.f / sval;
    for (int t = tid; t < TT; t += 1024)
        g_att[(size_t)b*TT + t] *= inv;
}

// ---------------- context vectors -------------------------------------------
__global__ void k_ctxt() {
    const int b = blockIdx.y;
    const int j = blockIdx.x*128 + threadIdx.x;
    const float* att = g_att + (size_t)b*TT;
    float aL = 0.f, aR = 0.f;
    for (int t = 0; t < TT; t += 4) {
        float a0 = att[t], a1 = att[t+1], a2 = att[t+2], a3 = att[t+3];
        const float* hl = g_hL + ((size_t)b*TT + t)*DD + j;
        const float* hr = g_hR + ((size_t)b*TT + t)*DD + j;
        aL += a0*hl[0] + a1*hl[DD] + a2*hl[2*DD] + a3*hl[3*DD];
        aR += a0*hr[0] + a1*hr[DD] + a2*hr[2*DD] + a3*hr[3*DD];
    }
    g_ctxtL[b*DD + j] = aL;
    g_ctxtR[b*DD + j] = aR;
}

// ---------------- output ----------------------------------------------------
__global__ void k_out(const float* __restrict__ WcyL, const float* __restrict__ WcyR,
                      float* __restrict__ out) {
    const int b = blockIdx.x;
    const int m = threadIdx.x >> 5;
    const int lane = threadIdx.x & 31;
    float s = 0.f;
    for (int j = lane; j < DD; j += 32)
        s += WcyL[m*DD + j]*g_ctxtL[b*DD + j] + WcyR[m*DD + j]*g_ctxtR[b*DD + j];
    #pragma unroll
    for (int o=16;o>0;o>>=1) s += __shfl_xor_sync(0xffffffffu, s, o);
    if (lane == 0) out[b*MOUT + m] = s;
}

// ---------------- launcher ---------------------------------------------------
extern "C" void kernel_launch(void* const* d_in, const int* in_sizes, int n_in,
                              void* d_out, int out_size) {
    const int*   toks = (const int*)  d_in[0];
    const float* emb  = (const float*)d_in[1];
    const float* Wxh  = (const float*)d_in[2];
    const float* Whh  = (const float*)d_in[3];
    const float* bxh  = (const float*)d_in[4];
    const float* bhh  = (const float*)d_in[5];
    const float* WcyL = (const float*)d_in[6];
    const float* WcyR = (const float*)d_in[7];
    float* out = (float*)d_out;
    (void)in_sizes; (void)n_in; (void)out_size;

    cudaFuncSetAttribute(k_recur, cudaFuncAttributeMaxDynamicSharedMemorySize,
                         SMEM_REC_BYTES);

    k_embed<<<(BATCH*TT*(EE/4) + 255)/256, 256>>>(toks, emb);
    k_whhr<<<(2*2*4096*512 + 255)/256, 256>>>(Whh);
    k_wx16<<<((2*2*GDIM*KINW)/4 + 255)/256, 256>>>(Wxh);

    for (int layer = 0; layer < 2; ++layer) {
        dim3 ggrid(GDIM/128, (BATCH*TT)/128, 2);
        k_gemm16<<<ggrid, 256>>>(bxh, bhh, layer);
        k_recur<<<RGRID, RTHREADS, SMEM_REC_BYTES>>>(layer);
        if (layer == 0)
            k_concat<<<(BATCH*TT*(KINW/4) + 255)/256, 256>>>();
    }

    k_dots<<<BATCH*TT, 256>>>();
    k_softmax<<<BATCH, 1024>>>();
    dim3 cgrid(DD/128, BATCH);
    k_ctxt<<<cgrid, 128>>>();
    k_out<<<BATCH, 64>>>(WcyL, WcyR, out);
}

// round 14
// speedup vs baseline: 2.9022x; 1.8516x over previous
#include <cuda_runtime.h>
#include <cuda_fp16.h>
#include <math.h>

// Problem constants
#define BATCH   4
#define TT      4096
#define EE      2048
#define DD      1024
#define GDIM    4096          // 4*DD gate rows
#define MOUT    2
#define KINW    2048          // input width per layer (E for l0, 2*DD for l1)

// Recurrence persistent-kernel config
#define RGRID    148
#define RTHREADS 256
#define NBD      74           // blocks per direction
#define UPB      14           // units per block (74*14 = 1036 >= 1024)

// Recurrence smem layout (dynamic)
#define SMEM_WA_H  (64*1032)          // A: 64 rows x 1032 halves (1024 + 8 pad)
#define SMEM_HB_H  (1024*8)           // B: 1024 k x 8 n halves
#define SMEM_C_F   (2*64*8)           // C partials per K-half
#define SMEM_REC_BYTES (SMEM_WA_H*2 + SMEM_HB_H*2 + SMEM_C_F*4)

// ---------------- scratch (static device arrays only; no allocation) ------
__device__ __align__(128) __half  g_xh  [BATCH*TT*KINW];      // fp16 layer input
__device__ __align__(128) __half  g_wxh16[2u*2u*GDIM*KINW];   // fp16 Wxh
__device__ __align__(128) __half  g_whh16r[2u*2u*GDIM*DD];    // fp16 Whh rows = j*4+g
__device__ __align__(128) float g_gx  [2u*BATCH*TT*GDIM];     // preacts [d][b][t][j][gate]
__device__ __align__(128) float g_hL  [BATCH*TT*DD];
__device__ __align__(128) float g_hR  [BATCH*TT*DD];
__device__ __align__(128) __half g_hc16[2][2][4*DD];          // h transport [buf][dir][k*4+b]
__device__ __align__(128) unsigned g_flags[RGRID*32];
__device__ float g_wv  [BATCH*TT];
__device__ float g_att [BATCH*TT];
__device__ float g_ctxtL[BATCH*DD];
__device__ float g_ctxtR[BATCH*DD];

// ---------------- scoped release/acquire primitives -----------------------
__device__ __forceinline__ unsigned ld_acq(unsigned* p) {
    unsigned v; asm volatile("ld.acquire.gpu.u32 %0, [%1];" : "=r"(v) : "l"(p) : "memory"); return v;
}
__device__ __forceinline__ void st_rel(unsigned* p, unsigned v) {
    asm volatile("st.release.gpu.u32 [%0], %1;" :: "l"(p), "r"(v) : "memory");
}

// ---------------- per-direction grid barrier: all blocks poll all flags ----
__device__ __forceinline__ void grid_barrier_dir(int d, int blk, unsigned* le) {
    const unsigned e = *le + 1u;
    __syncthreads();
    if (threadIdx.x == 0)
        st_rel(&g_flags[(d*NBD + blk)*32], e);
    if (threadIdx.x < NBD) {
        unsigned* f = &g_flags[(d*NBD + threadIdx.x)*32];
        while ((int)(ld_acq(f) - e) < 0) {}
    }
    __syncthreads();
    *le = e;
}

// ---------------- mma / ldmatrix / cp.async helpers ------------------------
__device__ __forceinline__ void ldsm4(unsigned& r0, unsigned& r1, unsigned& r2, unsigned& r3,
                                      const __half* p) {
    unsigned a = (unsigned)__cvta_generic_to_shared(p);
    asm volatile("ldmatrix.sync.aligned.m8n8.x4.shared.b16 {%0,%1,%2,%3}, [%4];"
                 : "=r"(r0), "=r"(r1), "=r"(r2), "=r"(r3) : "r"(a));
}
__device__ __forceinline__ void ldsm2t(unsigned& r0, unsigned& r1, const __half* p) {
    unsigned a = (unsigned)__cvta_generic_to_shared(p);
    asm volatile("ldmatrix.sync.aligned.m8n8.x2.trans.shared.b16 {%0,%1}, [%2];"
                 : "=r"(r0), "=r"(r1) : "r"(a));
}
__device__ __forceinline__ void mma16816(float* d, const unsigned* a, unsigned b0, unsigned b1) {
    asm volatile("mma.sync.aligned.m16n8k16.row.col.f32.f16.f16.f32 "
                 "{%0,%1,%2,%3},{%4,%5,%6,%7},{%8,%9},{%0,%1,%2,%3};"
                 : "+f"(d[0]), "+f"(d[1]), "+f"(d[2]), "+f"(d[3])
                 : "r"(a[0]), "r"(a[1]), "r"(a[2]), "r"(a[3]), "r"(b0), "r"(b1));
}
__device__ __forceinline__ void mma16816v(float* d, unsigned a0, unsigned a1, unsigned a2,
                                          unsigned a3, unsigned b0, unsigned b1) {
    asm volatile("mma.sync.aligned.m16n8k16.row.col.f32.f16.f16.f32 "
                 "{%0,%1,%2,%3},{%4,%5,%6,%7},{%8,%9},{%0,%1,%2,%3};"
                 : "+f"(d[0]), "+f"(d[1]), "+f"(d[2]), "+f"(d[3])
                 : "r"(a0), "r"(a1), "r"(a2), "r"(a3), "r"(b0), "r"(b1));
}
__device__ __forceinline__ void cpa16(const __half* dst_smem, const __half* src) {
    unsigned a = (unsigned)__cvta_generic_to_shared(dst_smem);
    asm volatile("cp.async.cg.shared.global [%0], [%1], 16;" :: "r"(a), "l"(src));
}
__device__ __forceinline__ void cpa_commit() { asm volatile("cp.async.commit_group;"); }
__device__ __forceinline__ void cpa_wait0()  { asm volatile("cp.async.wait_group 0;"); }
__device__ __forceinline__ void cpa_wait1()  { asm volatile("cp.async.wait_group 1;"); }

// ---------------- embedding gather -> fp16 ----------------
__global__ void k_embed(const int* __restrict__ toks, const float* __restrict__ emb) {
    int idx = blockIdx.x * blockDim.x + threadIdx.x;      // float4 granularity
    const int total = BATCH*TT*(EE/4);
    if (idx >= total) return;
    int row = idx / (EE/4);
    int c   = idx - row*(EE/4);
    int tok = toks[row];
    float4 v = reinterpret_cast<const float4*>(emb + (size_t)tok*EE)[c];
    __half2* o = reinterpret_cast<__half2*>(g_xh) + (size_t)idx*2;
    o[0] = __floats2half2_rn(v.x, v.y);
    o[1] = __floats2half2_rn(v.z, v.w);
}

// ---------------- Wxh -> fp16 ----------------
__global__ void k_wx16(const float* __restrict__ Wxh) {
    int idx = blockIdx.x * blockDim.x + threadIdx.x;      // float4 granularity
    const int total = (2*2*GDIM*KINW)/4;
    if (idx >= total) return;
    float4 v = reinterpret_cast<const float4*>(Wxh)[idx];
    __half2* o = reinterpret_cast<__half2*>(g_wxh16) + (size_t)idx*2;
    o[0] = __floats2half2_rn(v.x, v.y);
    o[1] = __floats2half2_rn(v.z, v.w);
}

// ---------------- Whh -> fp16, row-reordered: [ld][j*4+g][k] ---------------
__global__ void k_whhr(const float* __restrict__ Whh) {
    int idx = blockIdx.x * blockDim.x + threadIdx.x;      // half2 granularity
    const int total = 2*2*4096*512;
    if (idx >= total) return;
    int k2  = idx & 511;
    int row = (idx >> 9) & 4095;        // j*4 + g
    int ld  = idx >> 21;
    int j = row >> 2, g = row & 3;
    const float* src = Whh + ((size_t)ld*4096 + g*1024 + j)*1024 + k2*2;
    reinterpret_cast<__half2*>(g_whh16r)[idx] = __floats2half2_rn(src[0], src[1]);
}

// ---------------- tensor-core GEMM: gx = x(fp16) . W(fp16)^T + bias --------
#define GSTRIDE 40   // smem row stride in halves
__global__ __launch_bounds__(256) void k_gemm16(const float* __restrict__ bxh,
                                                const float* __restrict__ bhh,
                                                int layer) {
    const int d  = blockIdx.z;
    const int n0 = blockIdx.x * 128;
    const int m0 = blockIdx.y * 128;

    const __half* Bw = g_wxh16 + (size_t)(layer*2 + d) * GDIM * KINW;
    const float*  bx = bxh + (size_t)(layer*2 + d) * GDIM;
    const float*  bh = bhh + (size_t)(layer*2 + d) * GDIM;

    __shared__ __half As[2][128*GSTRIDE];
    __shared__ __half Bs[2][128*GSTRIDE];
    __shared__ float  sbias[128];

    const int tid  = threadIdx.x;
    const int warp = tid >> 5;
    const int lane = tid & 31;
    const int wm   = warp >> 1;
    const int wn   = warp & 1;

    const int bIdx  = m0 >> 12;
    const int sBase = m0 & (TT-1);

    if (tid < 128) sbias[tid] = bx[n0 + tid] + bh[n0 + tid];

    const __half* aSrc[2];
    const __half* bSrc[2];
    int smemOff[2];
    #pragma unroll
    for (int i = 0; i < 2; ++i) {
        int c  = tid + i*256;
        int r  = c >> 2;
        int kq = c & 3;
        int s    = sBase + r;
        int srow = d ? (TT-1-s) : s;
        aSrc[i] = g_xh + ((size_t)bIdx*TT + srow)*(size_t)KINW + kq*8;
        bSrc[i] = Bw   + (size_t)(n0 + r)*(size_t)KINW + kq*8;
        smemOff[i] = r*GSTRIDE + kq*8;
    }

    #define ISSUE(st) do { int _b = (st) & 1; size_t _k = (size_t)(st)*32;            \
        cpa16(&As[_b][smemOff[0]], aSrc[0] + _k); cpa16(&As[_b][smemOff[1]], aSrc[1] + _k); \
        cpa16(&Bs[_b][smemOff[0]], bSrc[0] + _k); cpa16(&Bs[_b][smemOff[1]], bSrc[1] + _k); \
        cpa_commit(); } while (0)

    float acc[2][8][4];
    #pragma unroll
    for (int mi=0;mi<2;mi++)
        #pragma unroll
        for (int ni=0;ni<8;ni++)
            #pragma unroll
            for (int q=0;q<4;q++) acc[mi][ni][q]=0.f;

    ISSUE(0);
    ISSUE(1);

    const int NSTAGE = KINW/32;   // 64
    for (int st = 0; st < NSTAGE; ++st) {
        if (st < NSTAGE-2) cpa_wait1(); else cpa_wait0();
        __syncthreads();

        const __half* Ab = As[st & 1];
        const __half* Bb = Bs[st & 1];
        #pragma unroll
        for (int ks = 0; ks < 2; ++ks) {
            unsigned af[2][4];
            #pragma unroll
            for (int mi = 0; mi < 2; ++mi) {
                int row = wm*32 + mi*16 + (lane & 7) + ((lane >> 3) & 1)*8;
                int col = ks*16 + (lane >> 4)*8;
                ldsm4(af[mi][0], af[mi][1], af[mi][2], af[mi][3], Ab + row*GSTRIDE + col);
            }
            unsigned bf[4][4];
            #pragma unroll
            for (int nj = 0; nj < 4; ++nj) {
                int g    = lane >> 3;
                int brow = wn*64 + nj*16 + (lane & 7) + ((g >> 1) & 1)*8;
                int bcol = ks*16 + (g & 1)*8;
                ldsm4(bf[nj][0], bf[nj][1], bf[nj][2], bf[nj][3], Bb + brow*GSTRIDE + bcol);
            }
            #pragma unroll
            for (int mi = 0; mi < 2; ++mi)
                #pragma unroll
                for (int ni = 0; ni < 8; ++ni)
                    mma16816(acc[mi][ni], af[mi],
                             bf[ni>>1][(ni&1)*2], bf[ni>>1][(ni&1)*2+1]);
        }
        __syncthreads();
        if (st + 2 < NSTAGE) ISSUE(st + 2);
    }
    #undef ISSUE

    #pragma unroll
    for (int mi = 0; mi < 2; ++mi) {
        int lrowBase = wm*32 + mi*16 + (lane >> 2);
        #pragma unroll
        for (int hf = 0; hf < 2; ++hf) {
            int lrow = lrowBase + hf*8;
            size_t rowbase = ((size_t)(d*BATCH + bIdx)*TT + sBase + lrow)*(size_t)GDIM;
            #pragma unroll
            for (int ni = 0; ni < 8; ++ni) {
                int lcol = wn*64 + ni*8 + (lane & 3)*2;
                float v0 = acc[mi][ni][hf*2+0] + sbias[lcol];
                float v1 = acc[mi][ni][hf*2+1] + sbias[lcol+1];
                int gn0 = n0 + lcol, gn1 = gn0 + 1;
                g_gx[rowbase + (size_t)(gn0 & 1023)*4 + (gn0 >> 10)] = v0;
                g_gx[rowbase + (size_t)(gn1 & 1023)*4 + (gn1 >> 10)] = v1;
            }
        }
    }
}

// ---------------- persistent biLSTM recurrence: tensor-core matvec ---------
// Block owns up to 14 units of ONE direction. A = Whh rows [unit*4+gate] in
// smem (loaded once). Per step: copy h (fp16, pre-transposed [k][4]) into
// HB[k][8], 8 warps split K (4 row-warps x 2 K-halves), 2 accumulator chains
// per warp, partial C's summed in the epilogue (56 threads -> gates + state).
__global__ __launch_bounds__(RTHREADS) void k_recur(int layer) {
    extern __shared__ char rsm[];
    __half* WA  = reinterpret_cast<__half*>(rsm);
    __half* HB  = reinterpret_cast<__half*>(rsm + SMEM_WA_H*2);
    float*  Csm = reinterpret_cast<float*> (rsm + SMEM_WA_H*2 + SMEM_HB_H*2);

    const int tid  = threadIdx.x;
    const int warp = tid >> 5;
    const int lane = tid & 31;
    const int d    = (blockIdx.x >= NBD) ? 1 : 0;
    const int blk  = blockIdx.x - d*NBD;
    const int base = blk * UPB;
    const int nU   = (DD - base < UPB) ? (DD - base) : UPB;   // 2..14
    const int nRows = nU * 4;

    // load recurrent weights into smem A (once), zero-pad rows to 64
    {
        const __half* Wsrc = g_whh16r + ((size_t)(layer*2 + d)*4096 + (size_t)base*4) * DD;
        for (int c = tid; c < 64*128; c += RTHREADS) {      // 16B chunks
            int row = c >> 7, q = c & 127;
            uint4 v = make_uint4(0u,0u,0u,0u);
            if (row < nRows)
                v = *(reinterpret_cast<const uint4*>(Wsrc + (size_t)row*DD) + q);
            *reinterpret_cast<uint4*>(WA + row*1032 + q*8) = v;
        }
    }
    // zero HB entirely (cols 4..7 stay zero forever)
    for (int i = tid; i < 1024; i += RTHREADS)
        reinterpret_cast<uint4*>(HB)[i] = make_uint4(0u,0u,0u,0u);
    // zero h buffer 0 for this direction (fp16 transport)
    for (int i = tid; i < (4*DD)/2; i += RTHREADS)
        reinterpret_cast<unsigned*>(g_hc16[0][d])[i] = 0u;

    unsigned localEpoch = ld_acq(&g_flags[(d*NBD + blk)*32]);
    grid_barrier_dir(d, blk, &localEpoch);

    const int lu = tid >> 2, bb = tid & 3;
    const bool fin = (tid < nRows);
    float creg = 0.f;
    const float4* gx4 = reinterpret_cast<const float4*>(g_gx);
    float* hist = d ? g_hR : g_hL;

    // per-warp static bases: wr = row-tile (0..3), kh = K-half (0..1)
    const int wr = warp & 3;
    const int kh = warp >> 2;
    const __half* Abase = WA + (size_t)(wr*16 + (lane & 7) + ((lane >> 3) & 1)*8) * 1032
                             + (lane >> 4)*8 + kh*512;
    const __half* Bbase = HB + (size_t)(kh*512 + (lane & 15)) * 8;

    for (int t = 0; t < TT; ++t) {
        const int rb = t & 1, wb = rb ^ 1;

        float4 pre = make_float4(0.f,0.f,0.f,0.f);
        if (fin)
            pre = __ldcg(gx4 + ((size_t)(d*BATCH + bb)*TT + t)*DD + (base + lu));

        // stage h: straight 8-byte copies (already fp16, already [k][4])
        {
            const uint2* hsrc = reinterpret_cast<const uint2*>(g_hc16[rb][d]);
            #pragma unroll
            for (int i = 0; i < 4; ++i) {
                int k = tid + i*256;
                uint2 v = __ldcg(hsrc + k);
                *reinterpret_cast<uint2*>(HB + (size_t)k*8) = v;
            }
        }
        __syncthreads();

        // mma: all 8 warps, 32 iters each, 2 independent accumulator chains
        {
            float c0[4] = {0.f,0.f,0.f,0.f};
            float c1[4] = {0.f,0.f,0.f,0.f};
            #pragma unroll
            for (int ks = 0; ks < 32; ks += 2) {
                unsigned a0,a1,a2,a3,b0,b1;
                ldsm4(a0, a1, a2, a3, Abase + (ks+0)*16);
                ldsm2t(b0, b1, Bbase + (size_t)(ks+0)*128);
                mma16816v(c0, a0, a1, a2, a3, b0, b1);
                ldsm4(a0, a1, a2, a3, Abase + (ks+1)*16);
                ldsm2t(b0, b1, Bbase + (size_t)(ks+1)*128);
                mma16816v(c1, a0, a1, a2, a3, b0, b1);
            }
            #pragma unroll
            for (int q = 0; q < 4; ++q) c0[q] += c1[q];
            int r  = wr*16 + (lane >> 2);
            int cc = (lane & 3)*2;
            float* Ck = Csm + kh*64*8;
            *reinterpret_cast<float2*>(&Ck[r*8 + cc])     = make_float2(c0[0], c0[1]);
            *reinterpret_cast<float2*>(&Ck[(r+8)*8 + cc]) = make_float2(c0[2], c0[3]);
        }
        __syncthreads();

        if (fin) {
            float pi = Csm[(lu*4+0)*8 + bb] + Csm[64*8 + (lu*4+0)*8 + bb] + pre.x;
            float pg = Csm[(lu*4+1)*8 + bb] + Csm[64*8 + (lu*4+1)*8 + bb] + pre.y;
            float pf = Csm[(lu*4+2)*8 + bb] + Csm[64*8 + (lu*4+2)*8 + bb] + pre.z;
            float po = Csm[(lu*4+3)*8 + bb] + Csm[64*8 + (lu*4+3)*8 + bb] + pre.w;
            float ii = 1.f/(1.f + __expf(-pi));
            float gg = 2.f/(1.f + __expf(-2.f*pg)) - 1.f;
            float ff = 1.f/(1.f + __expf(-pf));
            float oo = 1.f/(1.f + __expf(-po));
            float c  = ff*creg + ii*gg;
            creg = c;
            float th = 2.f/(1.f + __expf(-2.f*c)) - 1.f;
            float h  = oo * th;
            g_hc16[wb][d][(base + lu)*4 + bb] = __float2half_rn(h);
            hist[((size_t)bb*TT + t)*DD + base + lu] = h;
        }
        grid_barrier_dir(d, blk, &localEpoch);
    }
}

// ---------------- layer-1 input: x[b][t] = [hL[b][t], hR[b][T-1-t]] (fp16) -
__global__ void k_concat() {
    int idx = blockIdx.x * blockDim.x + threadIdx.x;    // float4 granularity
    const int total = BATCH*TT*(KINW/4);
    if (idx >= total) return;
    int c   = idx & (KINW/4 - 1);
    int row = idx >> 9;
    int b   = row >> 12;
    int t   = row & (TT-1);
    float4 v;
    if (c < DD/4) {
        v = reinterpret_cast<const float4*>(g_hL + ((size_t)b*TT + t)*DD)[c];
    } else {
        v = reinterpret_cast<const float4*>(g_hR + ((size_t)b*TT + (TT-1-t))*DD)[c - DD/4];
    }
    __half2* o = reinterpret_cast<__half2*>(g_xh) + (size_t)idx*2;
    o[0] = __floats2half2_rn(v.x, v.y);
    o[1] = __floats2half2_rn(v.z, v.w);
}

// ---------------- attention logits -----------------------------------------
__global__ void k_dots() {
    const int b = blockIdx.x >> 12;
    const int t = blockIdx.x & (TT-1);
    const int tid = threadIdx.x;
    const float* hl  = g_hL + ((size_t)b*TT + t)*DD;
    const float* hll = g_hL + ((size_t)b*TT + (TT-1))*DD;
    const float* hr  = g_hR + ((size_t)b*TT + t)*DD;
    const float* hrl = g_hR + ((size_t)b*TT + (TT-1))*DD;
    float s = 0.f;
    for (int j = tid; j < DD; j += 256)
        s += hl[j]*hll[j] + hr[j]*hrl[j];
    #pragma unroll
    for (int o=16;o>0;o>>=1) s += __shfl_xor_sync(0xffffffffu, s, o);
    __shared__ float red[8];
    if ((tid & 31) == 0) red[tid>>5] = s;
    __syncthreads();
    if (tid == 0) {
        float v = 0.f;
        #pragma unroll
        for (int w=0;w<8;w++) v += red[w];
        g_wv[(size_t)b*TT + t] = v * (1.f/64.f);   // 1/sqrt(4096)
    }
}

// ---------------- softmax per batch -----------------------------------------
__global__ void k_softmax() {
    const int b = blockIdx.x, tid = threadIdx.x;   // 1024 threads
    __shared__ float red[32];
    __shared__ float sval;
    const float* w = g_wv + (size_t)b*TT;
    float m = -1e30f;
    for (int t = tid; t < TT; t += 1024) m = fmaxf(m, w[t]);
    #pragma unroll
    for (int o=16;o>0;o>>=1) m = fmaxf(m, __shfl_xor_sync(0xffffffffu, m, o));
    if ((tid&31)==0) red[tid>>5] = m;
    __syncthreads();
    if (tid < 32) {
        float v = red[tid];
        #pragma unroll
        for (int o=16;o>0;o>>=1) v = fmaxf(v, __shfl_xor_sync(0xffffffffu, v, o));
        if (tid==0) sval = v;
    }
    __syncthreads();
    m = sval;
    float s = 0.f;
    for (int t = tid; t < TT; t += 1024) {
        float e = expf(w[t] - m);
        g_att[(size_t)b*TT + t] = e;
        s += e;
    }
    #pragma unroll
    for (int o=16;o>0;o>>=1) s += __shfl_xor_sync(0xffffffffu, s, o);
    __syncthreads();
    if ((tid&31)==0) red[tid>>5] = s;
    __syncthreads();
    if (tid < 32) {
        float v = red[tid];
        #pragma unroll
        for (int o=16;o>0;o>>=1) v += __shfl_xor_sync(0xffffffffu, v, o);
        if (tid==0) sval = v;
    }
    __syncthreads();
    float inv = 1.f / sval;
    for (int t = tid; t < TT; t += 1024)
        g_att[(size_t)b*TT + t] *= inv;
}

// ---------------- context vectors -------------------------------------------
__global__ void k_ctxt() {
    const int b = blockIdx.y;
    const int j = blockIdx.x*128 + threadIdx.x;
    const float* att = g_att + (size_t)b*TT;
    float aL = 0.f, aR = 0.f;
    for (int t = 0; t < TT; t += 4) {
        float a0 = att[t], a1 = att[t+1], a2 = att[t+2], a3 = att[t+3];
        const float* hl = g_hL + ((size_t)b*TT + t)*DD + j;
        const float* hr = g_hR + ((size_t)b*TT + t)*DD + j;
        aL += a0*hl[0] + a1*hl[DD] + a2*hl[2*DD] + a3*hl[3*DD];
        aR += a0*hr[0] + a1*hr[DD] + a2*hr[2*DD] + a3*hr[3*DD];
    }
    g_ctxtL[b*DD + j] = aL;
    g_ctxtR[b*DD + j] = aR;
}

// ---------------- output ----------------------------------------------------
__global__ void k_out(const float* __restrict__ WcyL, const float* __restrict__ WcyR,
                      float* __restrict__ out) {
    const int b = blockIdx.x;
    const int m = threadIdx.x >> 5;
    const int lane = threadIdx.x & 31;
    float s = 0.f;
    for (int j = lane; j < DD; j += 32)
        s += WcyL[m*DD + j]*g_ctxtL[b*DD + j] + WcyR[m*DD + j]*g_ctxtR[b*DD + j];
    #pragma unroll
    for (int o=16;o>0;o>>=1) s += __shfl_xor_sync(0xffffffffu, s, o);
    if (lane == 0) out[b*MOUT + m] = s;
}

// ---------------- launcher ---------------------------------------------------
extern "C" void kernel_launch(void* const* d_in, const int* in_sizes, int n_in,
                              void* d_out, int out_size) {
    const int*   toks = (const int*)  d_in[0];
    const float* emb  = (const float*)d_in[1];
    const float* Wxh  = (const float*)d_in[2];
    const float* Whh  = (const float*)d_in[3];
    const float* bxh  = (const float*)d_in[4];
    const float* bhh  = (const float*)d_in[5];
    const float* WcyL = (const float*)d_in[6];
    const float* WcyR = (const float*)d_in[7];
    float* out = (float*)d_out;
    (void)in_sizes; (void)n_in; (void)out_size;

    cudaFuncSetAttribute(k_recur, cudaFuncAttributeMaxDynamicSharedMemorySize,
                         SMEM_REC_BYTES);

    k_embed<<<(BATCH*TT*(EE/4) + 255)/256, 256>>>(toks, emb);
    k_whhr<<<(2*2*4096*512 + 255)/256, 256>>>(Whh);
    k_wx16<<<((2*2*GDIM*KINW)/4 + 255)/256, 256>>>(Wxh);

    for (int layer = 0; layer < 2; ++layer) {
        dim3 ggrid(GDIM/128, (BATCH*TT)/128, 2);
        k_gemm16<<<ggrid, 256>>>(bxh, bhh, layer);
        k_recur<<<RGRID, RTHREADS, SMEM_REC_BYTES>>>(layer);
        if (layer == 0)
            k_concat<<<(BATCH*TT*(KINW/4) + 255)/256, 256>>>();
    }

    k_dots<<<BATCH*TT, 256>>>();
    k_softmax<<<BATCH, 1024>>>();
    dim3 cgrid(DD/128, BATCH);
    k_ctxt<<<cgrid, 128>>>();
    k_out<<<BATCH, 64>>>(WcyL, WcyR, out);
}

// round 15
// speedup vs baseline: 2.9386x; 1.0125x over previous
#include <cuda_runtime.h>
#include <cuda_fp16.h>
#include <math.h>

// Problem constants
#define BATCH   4
#define TT      4096
#define EE      2048
#define DD      1024
#define GDIM    4096          // 4*DD gate rows
#define MOUT    2
#define KINW    2048          // input width per layer (E for l0, 2*DD for l1)

// Recurrence persistent-kernel config
#define RTHREADS 256
#define NBD      64           // blocks per direction
#define UPB      16           // units per block (64*16 = 1024 exactly)
#define RBLOCKS  (2*NBD)      // 128

// Recurrence smem layout (dynamic)
#define SMEM_WA_H  (64*1032)          // A: 64 rows x 1032 halves (1024 + 8 pad)
#define SMEM_HB_H  (1024*8)           // B: 1024 k x 8 n halves
#define SMEM_C_F   (2*64*8)           // C partials per K-half
#define SMEM_REC_BYTES (SMEM_WA_H*2 + SMEM_HB_H*2 + SMEM_C_F*4)

// ---------------- scratch (static device arrays only; no allocation) ------
__device__ __align__(128) __half  g_xh  [BATCH*TT*KINW];      // fp16 layer input
__device__ __align__(128) __half  g_wxh16[2u*2u*GDIM*KINW];   // fp16 Wxh
__device__ __align__(128) __half  g_whh16r[2u*2u*GDIM*DD];    // fp16 Whh rows = j*4+g
__device__ __align__(128) float g_gx  [2u*BATCH*TT*GDIM];     // preacts [d][b][t][j][gate]
__device__ __align__(128) float g_hL  [BATCH*TT*DD];
__device__ __align__(128) float g_hR  [BATCH*TT*DD];
__device__ __align__(128) __half g_hc16[2][2][4*DD];          // h transport [buf][dir][k*4+b]
__device__ __align__(128) unsigned g_flags[RBLOCKS*32];
__device__ float g_wv  [BATCH*TT];
__device__ float g_att [BATCH*TT];
__device__ float g_ctxtL[BATCH*DD];
__device__ float g_ctxtR[BATCH*DD];

// ---------------- scoped release/acquire primitives -----------------------
__device__ __forceinline__ unsigned ld_acq(unsigned* p) {
    unsigned v; asm volatile("ld.acquire.gpu.u32 %0, [%1];" : "=r"(v) : "l"(p) : "memory"); return v;
}
__device__ __forceinline__ void st_rel(unsigned* p, unsigned v) {
    asm volatile("st.release.gpu.u32 [%0], %1;" :: "l"(p), "r"(v) : "memory");
}

// ---------------- per-direction grid barrier: all blocks poll all flags ----
__device__ __forceinline__ void grid_barrier_dir(int d, int blk, unsigned* le) {
    const unsigned e = *le + 1u;
    __syncthreads();
    if (threadIdx.x == 0)
        st_rel(&g_flags[(d*NBD + blk)*32], e);
    if (threadIdx.x < NBD) {
        unsigned* f = &g_flags[(d*NBD + threadIdx.x)*32];
        while ((int)(ld_acq(f) - e) < 0) {}
    }
    __syncthreads();
    *le = e;
}

// ---------------- mma / ldmatrix / cp.async helpers ------------------------
__device__ __forceinline__ void ldsm4(unsigned& r0, unsigned& r1, unsigned& r2, unsigned& r3,
                                      const __half* p) {
    unsigned a = (unsigned)__cvta_generic_to_shared(p);
    asm volatile("ldmatrix.sync.aligned.m8n8.x4.shared.b16 {%0,%1,%2,%3}, [%4];"
                 : "=r"(r0), "=r"(r1), "=r"(r2), "=r"(r3) : "r"(a));
}
__device__ __forceinline__ void ldsm2t(unsigned& r0, unsigned& r1, const __half* p) {
    unsigned a = (unsigned)__cvta_generic_to_shared(p);
    asm volatile("ldmatrix.sync.aligned.m8n8.x2.trans.shared.b16 {%0,%1}, [%2];"
                 : "=r"(r0), "=r"(r1) : "r"(a));
}
__device__ __forceinline__ void mma16816(float* d, const unsigned* a, unsigned b0, unsigned b1) {
    asm volatile("mma.sync.aligned.m16n8k16.row.col.f32.f16.f16.f32 "
                 "{%0,%1,%2,%3},{%4,%5,%6,%7},{%8,%9},{%0,%1,%2,%3};"
                 : "+f"(d[0]), "+f"(d[1]), "+f"(d[2]), "+f"(d[3])
                 : "r"(a[0]), "r"(a[1]), "r"(a[2]), "r"(a[3]), "r"(b0), "r"(b1));
}
__device__ __forceinline__ void mma16816v(float* d, unsigned a0, unsigned a1, unsigned a2,
                                          unsigned a3, unsigned b0, unsigned b1) {
    asm volatile("mma.sync.aligned.m16n8k16.row.col.f32.f16.f16.f32 "
                 "{%0,%1,%2,%3},{%4,%5,%6,%7},{%8,%9},{%0,%1,%2,%3};"
                 : "+f"(d[0]), "+f"(d[1]), "+f"(d[2]), "+f"(d[3])
                 : "r"(a0), "r"(a1), "r"(a2), "r"(a3), "r"(b0), "r"(b1));
}
__device__ __forceinline__ void cpa16(const __half* dst_smem, const __half* src) {
    unsigned a = (unsigned)__cvta_generic_to_shared(dst_smem);
    asm volatile("cp.async.cg.shared.global [%0], [%1], 16;" :: "r"(a), "l"(src));
}
__device__ __forceinline__ void cpa_commit() { asm volatile("cp.async.commit_group;"); }
__device__ __forceinline__ void cpa_wait0()  { asm volatile("cp.async.wait_group 0;"); }
__device__ __forceinline__ void cpa_wait1()  { asm volatile("cp.async.wait_group 1;"); }

// ---------------- embedding gather -> fp16 ----------------
__global__ void k_embed(const int* __restrict__ toks, const float* __restrict__ emb) {
    int idx = blockIdx.x * blockDim.x + threadIdx.x;      // float4 granularity
    const int total = BATCH*TT*(EE/4);
    if (idx >= total) return;
    int row = idx / (EE/4);
    int c   = idx - row*(EE/4);
    int tok = toks[row];
    float4 v = reinterpret_cast<const float4*>(emb + (size_t)tok*EE)[c];
    __half2* o = reinterpret_cast<__half2*>(g_xh) + (size_t)idx*2;
    o[0] = __floats2half2_rn(v.x, v.y);
    o[1] = __floats2half2_rn(v.z, v.w);
}

// ---------------- Wxh -> fp16 ----------------
__global__ void k_wx16(const float* __restrict__ Wxh) {
    int idx = blockIdx.x * blockDim.x + threadIdx.x;      // float4 granularity
    const int total = (2*2*GDIM*KINW)/4;
    if (idx >= total) return;
    float4 v = reinterpret_cast<const float4*>(Wxh)[idx];
    __half2* o = reinterpret_cast<__half2*>(g_wxh16) + (size_t)idx*2;
    o[0] = __floats2half2_rn(v.x, v.y);
    o[1] = __floats2half2_rn(v.z, v.w);
}

// ---------------- Whh -> fp16, row-reordered: [ld][j*4+g][k] ---------------
__global__ void k_whhr(const float* __restrict__ Whh) {
    int idx = blockIdx.x * blockDim.x + threadIdx.x;      // half2 granularity
    const int total = 2*2*4096*512;
    if (idx >= total) return;
    int k2  = idx & 511;
    int row = (idx >> 9) & 4095;        // j*4 + g
    int ld  = idx >> 21;
    int j = row >> 2, g = row & 3;
    const float* src = Whh + ((size_t)ld*4096 + g*1024 + j)*1024 + k2*2;
    reinterpret_cast<__half2*>(g_whh16r)[idx] = __floats2half2_rn(src[0], src[1]);
}

// ---------------- tensor-core GEMM: gx = x(fp16) . W(fp16)^T + bias --------
#define GSTRIDE 40   // smem row stride in halves
__global__ __launch_bounds__(256) void k_gemm16(const float* __restrict__ bxh,
                                                const float* __restrict__ bhh,
                                                int layer) {
    const int d  = blockIdx.z;
    const int n0 = blockIdx.x * 128;
    const int m0 = blockIdx.y * 128;

    const __half* Bw = g_wxh16 + (size_t)(layer*2 + d) * GDIM * KINW;
    const float*  bx = bxh + (size_t)(layer*2 + d) * GDIM;
    const float*  bh = bhh + (size_t)(layer*2 + d) * GDIM;

    __shared__ __half As[2][128*GSTRIDE];
    __shared__ __half Bs[2][128*GSTRIDE];
    __shared__ float  sbias[128];

    const int tid  = threadIdx.x;
    const int warp = tid >> 5;
    const int lane = tid & 31;
    const int wm   = warp >> 1;
    const int wn   = warp & 1;

    const int bIdx  = m0 >> 12;
    const int sBase = m0 & (TT-1);

    if (tid < 128) sbias[tid] = bx[n0 + tid] + bh[n0 + tid];

    const __half* aSrc[2];
    const __half* bSrc[2];
    int smemOff[2];
    #pragma unroll
    for (int i = 0; i < 2; ++i) {
        int c  = tid + i*256;
        int r  = c >> 2;
        int kq = c & 3;
        int s    = sBase + r;
        int srow = d ? (TT-1-s) : s;
        aSrc[i] = g_xh + ((size_t)bIdx*TT + srow)*(size_t)KINW + kq*8;
        bSrc[i] = Bw   + (size_t)(n0 + r)*(size_t)KINW + kq*8;
        smemOff[i] = r*GSTRIDE + kq*8;
    }

    #define ISSUE(st) do { int _b = (st) & 1; size_t _k = (size_t)(st)*32;            \
        cpa16(&As[_b][smemOff[0]], aSrc[0] + _k); cpa16(&As[_b][smemOff[1]], aSrc[1] + _k); \
        cpa16(&Bs[_b][smemOff[0]], bSrc[0] + _k); cpa16(&Bs[_b][smemOff[1]], bSrc[1] + _k); \
        cpa_commit(); } while (0)

    float acc[2][8][4];
    #pragma unroll
    for (int mi=0;mi<2;mi++)
        #pragma unroll
        for (int ni=0;ni<8;ni++)
            #pragma unroll
            for (int q=0;q<4;q++) acc[mi][ni][q]=0.f;

    ISSUE(0);
    ISSUE(1);

    const int NSTAGE = KINW/32;   // 64
    for (int st = 0; st < NSTAGE; ++st) {
        if (st < NSTAGE-2) cpa_wait1(); else cpa_wait0();
        __syncthreads();

        const __half* Ab = As[st & 1];
        const __half* Bb = Bs[st & 1];
        #pragma unroll
        for (int ks = 0; ks < 2; ++ks) {
            unsigned af[2][4];
            #pragma unroll
            for (int mi = 0; mi < 2; ++mi) {
                int row = wm*32 + mi*16 + (lane & 7) + ((lane >> 3) & 1)*8;
                int col = ks*16 + (lane >> 4)*8;
                ldsm4(af[mi][0], af[mi][1], af[mi][2], af[mi][3], Ab + row*GSTRIDE + col);
            }
            unsigned bf[4][4];
            #pragma unroll
            for (int nj = 0; nj < 4; ++nj) {
                int g    = lane >> 3;
                int brow = wn*64 + nj*16 + (lane & 7) + ((g >> 1) & 1)*8;
                int bcol = ks*16 + (g & 1)*8;
                ldsm4(bf[nj][0], bf[nj][1], bf[nj][2], bf[nj][3], Bb + brow*GSTRIDE + bcol);
            }
            #pragma unroll
            for (int mi = 0; mi < 2; ++mi)
                #pragma unroll
                for (int ni = 0; ni < 8; ++ni)
                    mma16816(acc[mi][ni], af[mi],
                             bf[ni>>1][(ni&1)*2], bf[ni>>1][(ni&1)*2+1]);
        }
        __syncthreads();
        if (st + 2 < NSTAGE) ISSUE(st + 2);
    }
    #undef ISSUE

    #pragma unroll
    for (int mi = 0; mi < 2; ++mi) {
        int lrowBase = wm*32 + mi*16 + (lane >> 2);
        #pragma unroll
        for (int hf = 0; hf < 2; ++hf) {
            int lrow = lrowBase + hf*8;
            size_t rowbase = ((size_t)(d*BATCH + bIdx)*TT + sBase + lrow)*(size_t)GDIM;
            #pragma unroll
            for (int ni = 0; ni < 8; ++ni) {
                int lcol = wn*64 + ni*8 + (lane & 3)*2;
                float v0 = acc[mi][ni][hf*2+0] + sbias[lcol];
                float v1 = acc[mi][ni][hf*2+1] + sbias[lcol+1];
                int gn0 = n0 + lcol, gn1 = gn0 + 1;
                g_gx[rowbase + (size_t)(gn0 & 1023)*4 + (gn0 >> 10)] = v0;
                g_gx[rowbase + (size_t)(gn1 & 1023)*4 + (gn1 >> 10)] = v1;
            }
        }
    }
}

// ---------------- persistent biLSTM recurrence: tensor-core matvec ---------
// 64 blocks per direction, 16 units each (exact cover). A = Whh rows
// [unit*4+gate] in smem (loaded once). Per step: copy h (fp16, [k][4]) into
// HB[k][8], 8 warps split K (4 row-warps x 2 K-halves), 8 interleaved
// accumulator chains (dep depth 4), partial C summed in epilogue (64 threads
// = 16 units x 4 batches). History STG deferred past the flag release.
__global__ __launch_bounds__(RTHREADS) void k_recur(int layer) {
    extern __shared__ char rsm[];
    __half* WA  = reinterpret_cast<__half*>(rsm);
    __half* HB  = reinterpret_cast<__half*>(rsm + SMEM_WA_H*2);
    float*  Csm = reinterpret_cast<float*> (rsm + SMEM_WA_H*2 + SMEM_HB_H*2);

    const int tid  = threadIdx.x;
    const int warp = tid >> 5;
    const int lane = tid & 31;
    const int d    = (blockIdx.x >= NBD) ? 1 : 0;
    const int blk  = blockIdx.x - d*NBD;
    const int base = blk * UPB;          // 16 units, always full

    // load recurrent weights into smem A (once): 64 rows x 1024
    {
        const __half* Wsrc = g_whh16r + ((size_t)(layer*2 + d)*4096 + (size_t)base*4) * DD;
        for (int c = tid; c < 64*128; c += RTHREADS) {      // 16B chunks
            int row = c >> 7, q = c & 127;
            uint4 v = *(reinterpret_cast<const uint4*>(Wsrc + (size_t)row*DD) + q);
            *reinterpret_cast<uint4*>(WA + row*1032 + q*8) = v;
        }
    }
    // zero HB entirely (cols 4..7 stay zero forever)
    for (int i = tid; i < 1024; i += RTHREADS)
        reinterpret_cast<uint4*>(HB)[i] = make_uint4(0u,0u,0u,0u);
    // zero h buffer 0 for this direction (fp16 transport)
    for (int i = tid; i < (4*DD)/2; i += RTHREADS)
        reinterpret_cast<unsigned*>(g_hc16[0][d])[i] = 0u;

    unsigned localEpoch = ld_acq(&g_flags[(d*NBD + blk)*32]);
    grid_barrier_dir(d, blk, &localEpoch);

    const int lu = tid >> 2, bb = tid & 3;       // tid<64: (unit, batch)
    const bool fin = (tid < 64);
    float creg = 0.f;
    const float4* gx4 = reinterpret_cast<const float4*>(g_gx);
    float* hist = d ? g_hR : g_hL;

    // per-warp static bases: wr = row-tile (0..3), kh = K-half (0..1)
    const int wr = warp & 3;
    const int kh = warp >> 2;
    const __half* Abase = WA + (size_t)(wr*16 + (lane & 7) + ((lane >> 3) & 1)*8) * 1032
                             + (lane >> 4)*8 + kh*512;
    const __half* Bbase = HB + (size_t)(kh*512 + (lane & 15)) * 8;

    for (int t = 0; t < TT; ++t) {
        const int rb = t & 1, wb = rb ^ 1;

        float4 pre = make_float4(0.f,0.f,0.f,0.f);
        if (fin)
            pre = __ldcg(gx4 + ((size_t)(d*BATCH + bb)*TT + t)*DD + (base + lu));

        // stage h: straight 8-byte copies (already fp16, already [k][4])
        {
            const uint2* hsrc = reinterpret_cast<const uint2*>(g_hc16[rb][d]);
            #pragma unroll
            for (int i = 0; i < 4; ++i) {
                int k = tid + i*256;
                uint2 v = __ldcg(hsrc + k);
                *reinterpret_cast<uint2*>(HB + (size_t)k*8) = v;
            }
        }
        __syncthreads();

        // mma: all 8 warps, 32 iters each, 8 interleaved accumulator chains
        {
            float cc[8][4];
            #pragma unroll
            for (int q = 0; q < 8; ++q)
                #pragma unroll
                for (int w = 0; w < 4; ++w) cc[q][w] = 0.f;
            #pragma unroll
            for (int ks = 0; ks < 32; ++ks) {
                unsigned a0,a1,a2,a3,b0,b1;
                ldsm4(a0, a1, a2, a3, Abase + ks*16);
                ldsm2t(b0, b1, Bbase + (size_t)ks*128);
                mma16816v(cc[ks & 7], a0, a1, a2, a3, b0, b1);
            }
            #pragma unroll
            for (int q = 0; q < 4; ++q) {
                #pragma unroll
                for (int w = 0; w < 4; ++w)
                    cc[q][w] += cc[q+4][w];
            }
            #pragma unroll
            for (int w = 0; w < 4; ++w)
                cc[0][w] = (cc[0][w] + cc[1][w]) + (cc[2][w] + cc[3][w]);

            int r  = wr*16 + (lane >> 2);
            int ccol = (lane & 3)*2;
            float* Ck = Csm + kh*64*8;
            *reinterpret_cast<float2*>(&Ck[r*8 + ccol])     = make_float2(cc[0][0], cc[0][1]);
            *reinterpret_cast<float2*>(&Ck[(r+8)*8 + ccol]) = make_float2(cc[0][2], cc[0][3]);
        }
        __syncthreads();

        float hval = 0.f;
        if (fin) {
            float pi = Csm[(lu*4+0)*8 + bb] + Csm[64*8 + (lu*4+0)*8 + bb] + pre.x;
            float pg = Csm[(lu*4+1)*8 + bb] + Csm[64*8 + (lu*4+1)*8 + bb] + pre.y;
            float pf = Csm[(lu*4+2)*8 + bb] + Csm[64*8 + (lu*4+2)*8 + bb] + pre.z;
            float po = Csm[(lu*4+3)*8 + bb] + Csm[64*8 + (lu*4+3)*8 + bb] + pre.w;
            float ii = 1.f/(1.f + __expf(-pi));
            float gg = 2.f/(1.f + __expf(-2.f*pg)) - 1.f;
            float ff = 1.f/(1.f + __expf(-pf));
            float oo = 1.f/(1.f + __expf(-po));
            float c  = ff*creg + ii*gg;
            creg = c;
            float th = 2.f/(1.f + __expf(-2.f*c)) - 1.f;
            hval = oo * th;
            g_hc16[wb][d][(base + lu)*4 + bb] = __float2half_rn(hval);
        }
        grid_barrier_dir(d, blk, &localEpoch);
        // history store AFTER the flag release: off the critical sync path
        if (fin)
            hist[((size_t)bb*TT + t)*DD + base + lu] = hval;
    }
}

// ---------------- layer-1 input: x[b][t] = [hL[b][t], hR[b][T-1-t]] (fp16) -
__global__ void k_concat() {
    int idx = blockIdx.x * blockDim.x + threadIdx.x;    // float4 granularity
    const int total = BATCH*TT*(KINW/4);
    if (idx >= total) return;
    int c   = idx & (KINW/4 - 1);
    int row = idx >> 9;
    int b   = row >> 12;
    int t   = row & (TT-1);
    float4 v;
    if (c < DD/4) {
        v = reinterpret_cast<const float4*>(g_hL + ((size_t)b*TT + t)*DD)[c];
    } else {
        v = reinterpret_cast<const float4*>(g_hR + ((size_t)b*TT + (TT-1-t))*DD)[c - DD/4];
    }
    __half2* o = reinterpret_cast<__half2*>(g_xh) + (size_t)idx*2;
    o[0] = __floats2half2_rn(v.x, v.y);
    o[1] = __floats2half2_rn(v.z, v.w);
}

// ---------------- attention logits -----------------------------------------
__global__ void k_dots() {
    const int b = blockIdx.x >> 12;
    const int t = blockIdx.x & (TT-1);
    const int tid = threadIdx.x;
    const float* hl  = g_hL + ((size_t)b*TT + t)*DD;
    const float* hll = g_hL + ((size_t)b*TT + (TT-1))*DD;
    const float* hr  = g_hR + ((size_t)b*TT + t)*DD;
    const float* hrl = g_hR + ((size_t)b*TT + (TT-1))*DD;
    float s = 0.f;
    for (int j = tid; j < DD; j += 256)
        s += hl[j]*hll[j] + hr[j]*hrl[j];
    #pragma unroll
    for (int o=16;o>0;o>>=1) s += __shfl_xor_sync(0xffffffffu, s, o);
    __shared__ float red[8];
    if ((tid & 31) == 0) red[tid>>5] = s;
    __syncthreads();
    if (tid == 0) {
        float v = 0.f;
        #pragma unroll
        for (int w=0;w<8;w++) v += red[w];
        g_wv[(size_t)b*TT + t] = v * (1.f/64.f);   // 1/sqrt(4096)
    }
}

// ---------------- softmax per batch -----------------------------------------
__global__ void k_softmax() {
    const int b = blockIdx.x, tid = threadIdx.x;   // 1024 threads
    __shared__ float red[32];
    __shared__ float sval;
    const float* w = g_wv + (size_t)b*TT;
    float m = -1e30f;
    for (int t = tid; t < TT; t += 1024) m = fmaxf(m, w[t]);
    #pragma unroll
    for (int o=16;o>0;o>>=1) m = fmaxf(m, __shfl_xor_sync(0xffffffffu, m, o));
    if ((tid&31)==0) red[tid>>5] = m;
    __syncthreads();
    if (tid < 32) {
        float v = red[tid];
        #pragma unroll
        for (int o=16;o>0;o>>=1) v = fmaxf(v, __shfl_xor_sync(0xffffffffu, v, o));
        if (tid==0) sval = v;
    }
    __syncthreads();
    m = sval;
    float s = 0.f;
    for (int t = tid; t < TT; t += 1024) {
        float e = expf(w[t] - m);
        g_att[(size_t)b*TT + t] = e;
        s += e;
    }
    #pragma unroll
    for (int o=16;o>0;o>>=1) s += __shfl_xor_sync(0xffffffffu, s, o);
    __syncthreads();
    if ((tid&31)==0) red[tid>>5] = s;
    __syncthreads();
    if (tid < 32) {
        float v = red[tid];
        #pragma unroll
        for (int o=16;o>0;o>>=1) v += __shfl_xor_sync(0xffffffffu, v, o);
        if (tid==0) sval = v;
    }
    __syncthreads();
    float inv = 1.f / sval;
    for (int t = tid; t < TT; t += 1024)
        g_att[(size_t)b*TT + t] *= inv;
}

// ---------------- context vectors -------------------------------------------
__global__ void k_ctxt() {
    const int b = blockIdx.y;
    const int j = blockIdx.x*128 + threadIdx.x;
    const float* att = g_att + (size_t)b*TT;
    float aL = 0.f, aR = 0.f;
    for (int t = 0; t < TT; t += 4) {
        float a0 = att[t], a1 = att[t+1], a2 = att[t+2], a3 = att[t+3];
        const float* hl = g_hL + ((size_t)b*TT + t)*DD + j;
        const float* hr = g_hR + ((size_t)b*TT + t)*DD + j;
        aL += a0*hl[0] + a1*hl[DD] + a2*hl[2*DD] + a3*hl[3*DD];
        aR += a0*hr[0] + a1*hr[DD] + a2*hr[2*DD] + a3*hr[3*DD];
    }
    g_ctxtL[b*DD + j] = aL;
    g_ctxtR[b*DD + j] = aR;
}

// ---------------- output ----------------------------------------------------
__global__ void k_out(const float* __restrict__ WcyL, const float* __restrict__ WcyR,
                      float* __restrict__ out) {
    const int b = blockIdx.x;
    const int m = threadIdx.x >> 5;
    const int lane = threadIdx.x & 31;
    float s = 0.f;
    for (int j = lane; j < DD; j += 32)
        s += WcyL[m*DD + j]*g_ctxtL[b*DD + j] + WcyR[m*DD + j]*g_ctxtR[b*DD + j];
    #pragma unroll
    for (int o=16;o>0;o>>=1) s += __shfl_xor_sync(0xffffffffu, s, o);
    if (lane == 0) out[b*MOUT + m] = s;
}

// ---------------- launcher ---------------------------------------------------
extern "C" void kernel_launch(void* const* d_in, const int* in_sizes, int n_in,
                              void* d_out, int out_size) {
    const int*   toks = (const int*)  d_in[0];
    const float* emb  = (const float*)d_in[1];
    const float* Wxh  = (const float*)d_in[2];
    const float* Whh  = (const float*)d_in[3];
    const float* bxh  = (const float*)d_in[4];
    const float* bhh  = (const float*)d_in[5];
    const float* WcyL = (const float*)d_in[6];
    const float* WcyR = (const float*)d_in[7];
    float* out = (float*)d_out;
    (void)in_sizes; (void)n_in; (void)out_size;

    cudaFuncSetAttribute(k_recur, cudaFuncAttributeMaxDynamicSharedMemorySize,
                         SMEM_REC_BYTES);

    k_embed<<<(BATCH*TT*(EE/4) + 255)/256, 256>>>(toks, emb);
    k_whhr<<<(2*2*4096*512 + 255)/256, 256>>>(Whh);
    k_wx16<<<((2*2*GDIM*KINW)/4 + 255)/256, 256>>>(Wxh);

    for (int layer = 0; layer < 2; ++layer) {
        dim3 ggrid(GDIM/128, (BATCH*TT)/128, 2);
        k_gemm16<<<ggrid, 256>>>(bxh, bhh, layer);
        k_recur<<<RBLOCKS, RTHREADS, SMEM_REC_BYTES>>>(layer);
        if (layer == 0)
            k_concat<<<(BATCH*TT*(KINW/4) + 255)/256, 256>>>();
    }

    k_dots<<<BATCH*TT, 256>>>();
    k_softmax<<<BATCH, 1024>>>();
    dim3 cgrid(DD/128, BATCH);
    k_ctxt<<<cgrid, 128>>>();
    k_out<<<BATCH, 64>>>(WcyL, WcyR, out);
}

// round 17
// speedup vs baseline: 3.3192x; 1.1295x over previous
#include <cuda_runtime.h>
#include <cuda_fp16.h>
#include <math.h>

// Problem constants
#define BATCH   4
#define TT      4096
#define EE      2048
#define DD      1024
#define GDIM    4096          // 4*DD gate rows
#define MOUT    2
#define KINW    2048          // input width per layer (E for l0, 2*DD for l1)

// Recurrence persistent-kernel config
#define RTHREADS 512          // 16 warps: 4 row-groups x 4 K-quarters
#define NBD      64           // blocks per direction
#define UPB      16           // units per block (64*16 = 1024 exactly)
#define RBLOCKS  (2*NBD)      // 128

// Recurrence smem layout (dynamic)
#define SMEM_WA_H  (64*1032)          // A staging: 64 rows x 1032 halves
#define SMEM_HB_H  (1024*8)           // B: 1024 k x 8 n halves
#define SMEM_C_F   (4*64*8)           // C partials per K-quarter
#define SMEM_REC_BYTES (SMEM_WA_H*2 + SMEM_HB_H*2 + SMEM_C_F*4)

// ---------------- scratch (static device arrays only; no allocation) ------
__device__ __align__(128) __half  g_xh  [BATCH*TT*KINW];      // fp16 layer input
__device__ __align__(128) __half  g_wxh16[2u*2u*GDIM*KINW];   // fp16 Wxh
__device__ __align__(128) __half  g_whh16r[2u*2u*GDIM*DD];    // fp16 Whh rows = j*4+g
__device__ __align__(128) float g_gx  [2u*BATCH*TT*GDIM];     // preacts [d][b][t][j][gate]
__device__ __align__(128) float g_hL  [BATCH*TT*DD];
__device__ __align__(128) float g_hR  [BATCH*TT*DD];
__device__ __align__(128) __half g_hc16[2][2][4*DD];          // h transport [buf][dir][k*4+b]
__device__ __align__(128) unsigned g_flags[RBLOCKS*32];
__device__ float g_wv  [BATCH*TT];
__device__ float g_att [BATCH*TT];
__device__ float g_ctxtL[BATCH*DD];
__device__ float g_ctxtR[BATCH*DD];

// ---------------- scoped release/acquire primitives -----------------------
__device__ __forceinline__ unsigned ld_acq(unsigned* p) {
    unsigned v; asm volatile("ld.acquire.gpu.u32 %0, [%1];" : "=r"(v) : "l"(p) : "memory"); return v;
}
__device__ __forceinline__ void st_rel(unsigned* p, unsigned v) {
    asm volatile("st.release.gpu.u32 [%0], %1;" :: "l"(p), "r"(v) : "memory");
}

// ---------------- per-direction grid barrier: all blocks poll all flags ----
__device__ __forceinline__ void grid_barrier_dir(int d, int blk, unsigned* le) {
    const unsigned e = *le + 1u;
    __syncthreads();
    if (threadIdx.x == 0)
        st_rel(&g_flags[(d*NBD + blk)*32], e);
    if (threadIdx.x < NBD) {
        unsigned* f = &g_flags[(d*NBD + threadIdx.x)*32];
        while ((int)(ld_acq(f) - e) < 0) {}
    }
    __syncthreads();
    *le = e;
}

// ---------------- mma / ldmatrix / cp.async helpers ------------------------
__device__ __forceinline__ void ldsm4(unsigned& r0, unsigned& r1, unsigned& r2, unsigned& r3,
                                      const __half* p) {
    unsigned a = (unsigned)__cvta_generic_to_shared(p);
    asm volatile("ldmatrix.sync.aligned.m8n8.x4.shared.b16 {%0,%1,%2,%3}, [%4];"
                 : "=r"(r0), "=r"(r1), "=r"(r2), "=r"(r3) : "r"(a));
}
__device__ __forceinline__ void ldsm2t(unsigned& r0, unsigned& r1, const __half* p) {
    unsigned a = (unsigned)__cvta_generic_to_shared(p);
    asm volatile("ldmatrix.sync.aligned.m8n8.x2.trans.shared.b16 {%0,%1}, [%2];"
                 : "=r"(r0), "=r"(r1) : "r"(a));
}
__device__ __forceinline__ void mma16816(float* d, const unsigned* a, unsigned b0, unsigned b1) {
    asm volatile("mma.sync.aligned.m16n8k16.row.col.f32.f16.f16.f32 "
                 "{%0,%1,%2,%3},{%4,%5,%6,%7},{%8,%9},{%0,%1,%2,%3};"
                 : "+f"(d[0]), "+f"(d[1]), "+f"(d[2]), "+f"(d[3])
                 : "r"(a[0]), "r"(a[1]), "r"(a[2]), "r"(a[3]), "r"(b0), "r"(b1));
}
__device__ __forceinline__ void cpa16(const __half* dst_smem, const __half* src) {
    unsigned a = (unsigned)__cvta_generic_to_shared(dst_smem);
    asm volatile("cp.async.cg.shared.global [%0], [%1], 16;" :: "r"(a), "l"(src));
}
__device__ __forceinline__ void cpa_commit() { asm volatile("cp.async.commit_group;"); }
__device__ __forceinline__ void cpa_wait0()  { asm volatile("cp.async.wait_group 0;"); }
__device__ __forceinline__ void cpa_wait1()  { asm volatile("cp.async.wait_group 1;"); }

// ---------------- embedding gather -> fp16 ----------------
__global__ void k_embed(const int* __restrict__ toks, const float* __restrict__ emb) {
    int idx = blockIdx.x * blockDim.x + threadIdx.x;      // float4 granularity
    const int total = BATCH*TT*(EE/4);
    if (idx >= total) return;
    int row = idx / (EE/4);
    int c   = idx - row*(EE/4);
    int tok = toks[row];
    float4 v = reinterpret_cast<const float4*>(emb + (size_t)tok*EE)[c];
    __half2* o = reinterpret_cast<__half2*>(g_xh) + (size_t)idx*2;
    o[0] = __floats2half2_rn(v.x, v.y);
    o[1] = __floats2half2_rn(v.z, v.w);
}

// ---------------- Wxh -> fp16 ----------------
__global__ void k_wx16(const float* __restrict__ Wxh) {
    int idx = blockIdx.x * blockDim.x + threadIdx.x;      // float4 granularity
    const int total = (2*2*GDIM*KINW)/4;
    if (idx >= total) return;
    float4 v = reinterpret_cast<const float4*>(Wxh)[idx];
    __half2* o = reinterpret_cast<__half2*>(g_wxh16) + (size_t)idx*2;
    o[0] = __floats2half2_rn(v.x, v.y);
    o[1] = __floats2half2_rn(v.z, v.w);
}

// ---------------- Whh -> fp16, row-reordered: [ld][j*4+g][k] ---------------
__global__ void k_whhr(const float* __restrict__ Whh) {
    int idx = blockIdx.x * blockDim.x + threadIdx.x;      // half2 granularity
    const int total = 2*2*4096*512;
    if (idx >= total) return;
    int k2  = idx & 511;
    int row = (idx >> 9) & 4095;        // j*4 + g
    int ld  = idx >> 21;
    int j = row >> 2, g = row & 3;
    const float* src = Whh + ((size_t)ld*4096 + g*1024 + j)*1024 + k2*2;
    reinterpret_cast<__half2*>(g_whh16r)[idx] = __floats2half2_rn(src[0], src[1]);
}

// ---------------- tensor-core GEMM: gx = x(fp16) . W(fp16)^T + bias --------
#define GSTRIDE 40   // smem row stride in halves
__global__ __launch_bounds__(256) void k_gemm16(const float* __restrict__ bxh,
                                                const float* __restrict__ bhh,
                                                int layer) {
    const int d  = blockIdx.z;
    const int n0 = blockIdx.x * 128;
    const int m0 = blockIdx.y * 128;

    const __half* Bw = g_wxh16 + (size_t)(layer*2 + d) * GDIM * KINW;
    const float*  bx = bxh + (size_t)(layer*2 + d) * GDIM;
    const float*  bh = bhh + (size_t)(layer*2 + d) * GDIM;

    __shared__ __half As[2][128*GSTRIDE];
    __shared__ __half Bs[2][128*GSTRIDE];
    __shared__ float  sbias[128];

    const int tid  = threadIdx.x;
    const int warp = tid >> 5;
    const int lane = tid & 31;
    const int wm   = warp >> 1;
    const int wn   = warp & 1;

    const int bIdx  = m0 >> 12;
    const int sBase = m0 & (TT-1);

    if (tid < 128) sbias[tid] = bx[n0 + tid] + bh[n0 + tid];

    const __half* aSrc[2];
    const __half* bSrc[2];
    int smemOff[2];
    #pragma unroll
    for (int i = 0; i < 2; ++i) {
        int c  = tid + i*256;
        int r  = c >> 2;
        int kq = c & 3;
        int s    = sBase + r;
        int srow = d ? (TT-1-s) : s;
        aSrc[i] = g_xh + ((size_t)bIdx*TT + srow)*(size_t)KINW + kq*8;
        bSrc[i] = Bw   + (size_t)(n0 + r)*(size_t)KINW + kq*8;
        smemOff[i] = r*GSTRIDE + kq*8;
    }

    #define ISSUE(st) do { int _b = (st) & 1; size_t _k = (size_t)(st)*32;            \
        cpa16(&As[_b][smemOff[0]], aSrc[0] + _k); cpa16(&As[_b][smemOff[1]], aSrc[1] + _k); \
        cpa16(&Bs[_b][smemOff[0]], bSrc[0] + _k); cpa16(&Bs[_b][smemOff[1]], bSrc[1] + _k); \
        cpa_commit(); } while (0)

    float acc[2][8][4];
    #pragma unroll
    for (int mi=0;mi<2;mi++)
        #pragma unroll
        for (int ni=0;ni<8;ni++)
            #pragma unroll
            for (int q=0;q<4;q++) acc[mi][ni][q]=0.f;

    ISSUE(0);
    ISSUE(1);

    const int NSTAGE = KINW/32;   // 64
    for (int st = 0; st < NSTAGE; ++st) {
        if (st < NSTAGE-2) cpa_wait1(); else cpa_wait0();
        __syncthreads();

        const __half* Ab = As[st & 1];
        const __half* Bb = Bs[st & 1];
        #pragma unroll
        for (int ks = 0; ks < 2; ++ks) {
            unsigned af[2][4];
            #pragma unroll
            for (int mi = 0; mi < 2; ++mi) {
                int row = wm*32 + mi*16 + (lane & 7) + ((lane >> 3) & 1)*8;
                int col = ks*16 + (lane >> 4)*8;
                ldsm4(af[mi][0], af[mi][1], af[mi][2], af[mi][3], Ab + row*GSTRIDE + col);
            }
            unsigned bf[4][4];
            #pragma unroll
            for (int nj = 0; nj < 4; ++nj) {
                int g    = lane >> 3;
                int brow = wn*64 + nj*16 + (lane & 7) + ((g >> 1) & 1)*8;
                int bcol = ks*16 + (g & 1)*8;
                ldsm4(bf[nj][0], bf[nj][1], bf[nj][2], bf[nj][3], Bb + brow*GSTRIDE + bcol);
            }
            #pragma unroll
            for (int mi = 0; mi < 2; ++mi)
                #pragma unroll
                for (int ni = 0; ni < 8; ++ni)
                    mma16816(acc[mi][ni], af[mi],
                             bf[ni>>1][(ni&1)*2], bf[ni>>1][(ni&1)*2+1]);
        }
        __syncthreads();
        if (st + 2 < NSTAGE) ISSUE(st + 2);
    }
    #undef ISSUE

    #pragma unroll
    for (int mi = 0; mi < 2; ++mi) {
        int lrowBase = wm*32 + mi*16 + (lane >> 2);
        #pragma unroll
        for (int hf = 0; hf < 2; ++hf) {
            int lrow = lrowBase + hf*8;
            size_t rowbase = ((size_t)(d*BATCH + bIdx)*TT + sBase + lrow)*(size_t)GDIM;
            #pragma unroll
            for (int ni = 0; ni < 8; ++ni) {
                int lcol = wn*64 + ni*8 + (lane & 3)*2;
                float v0 = acc[mi][ni][hf*2+0] + sbias[lcol];
                float v1 = acc[mi][ni][hf*2+1] + sbias[lcol+1];
                int gn0 = n0 + lcol, gn1 = gn0 + 1;
                g_gx[rowbase + (size_t)(gn0 & 1023)*4 + (gn0 >> 10)] = v0;
                g_gx[rowbase + (size_t)(gn1 & 1023)*4 + (gn1 >> 10)] = v1;
            }
        }
    }
}

// ---------------- persistent biLSTM recurrence: A-frags in registers -------
// 64 blocks/dir x 16 units. 16 warps = 4 row-groups x 4 K-quarters; each warp
// preloads its 16 k16 A-fragments (64 regs) ONCE, so the per-step mma phase
// reads only B from smem. 4 interleaved accumulator chains; 4 K-partial C
// tiles summed in the 64-thread epilogue.
__global__ __launch_bounds__(RTHREADS, 1) void k_recur(int layer) {
    extern __shared__ char rsm[];
    __half* WA  = reinterpret_cast<__half*>(rsm);
    __half* HB  = reinterpret_cast<__half*>(rsm + SMEM_WA_H*2);
    float*  Csm = reinterpret_cast<float*> (rsm + SMEM_WA_H*2 + SMEM_HB_H*2);

    const int tid  = threadIdx.x;
    const int warp = tid >> 5;
    const int lane = tid & 31;
    const int d    = (blockIdx.x >= NBD) ? 1 : 0;
    const int blk  = blockIdx.x - d*NBD;
    const int base = blk * UPB;          // 16 units, always full

    // stage recurrent weights into smem once: 64 rows x 1024 (row stride 1032)
    {
        const __half* Wsrc = g_whh16r + ((size_t)(layer*2 + d)*4096 + (size_t)base*4) * DD;
        for (int c = tid; c < 64*128; c += RTHREADS) {      // 16B chunks
            int row = c >> 7, q = c & 127;
            uint4 v = *(reinterpret_cast<const uint4*>(Wsrc + (size_t)row*DD) + q);
            *reinterpret_cast<uint4*>(WA + row*1032 + q*8) = v;
        }
    }
    // zero HB entirely (cols 4..7 stay zero forever)
    for (int i = tid; i < 1024; i += RTHREADS)
        reinterpret_cast<uint4*>(HB)[i] = make_uint4(0u,0u,0u,0u);
    // zero h buffer 0 for this direction (fp16 transport)
    for (int i = tid; i < (4*DD)/2; i += RTHREADS)
        reinterpret_cast<unsigned*>(g_hc16[0][d])[i] = 0u;
    __syncthreads();

    // per-warp geometry: wr = row-group (0..3), kq = K-quarter (0..3)
    const int wr = warp & 3;
    const int kq = warp >> 2;
    const __half* Abase = WA + (size_t)(wr*16 + (lane & 7) + ((lane >> 3) & 1)*8) * 1032
                             + (lane >> 4)*8 + kq*256;
    const __half* Bbase = HB + (size_t)(kq*256 + (lane & 15)) * 8;

    // preload A fragments for all 16 k16 slices of this warp's K-quarter
    unsigned af[16][4];
    #pragma unroll
    for (int ks = 0; ks < 16; ++ks)
        ldsm4(af[ks][0], af[ks][1], af[ks][2], af[ks][3], Abase + ks*16);

    unsigned localEpoch = ld_acq(&g_flags[(d*NBD + blk)*32]);
    grid_barrier_dir(d, blk, &localEpoch);

    const int lu = tid >> 2, bb = tid & 3;       // tid<64: (unit, batch)
    const bool fin = (tid < 64);
    float creg = 0.f;
    const float4* gx4 = reinterpret_cast<const float4*>(g_gx);
    float* hist = d ? g_hR : g_hL;

    for (int t = 0; t < TT; ++t) {
        const int rb = t & 1, wb = rb ^ 1;

        float4 pre = make_float4(0.f,0.f,0.f,0.f);
        if (fin)
            pre = __ldcg(gx4 + ((size_t)(d*BATCH + bb)*TT + t)*DD + (base + lu));

        // stage h: 8KB into HB rows (8 bytes into each 16-byte [k][8] row)
        {
            const uint2* hsrc = reinterpret_cast<const uint2*>(g_hc16[rb][d]);
            #pragma unroll
            for (int i = 0; i < 2; ++i) {
                int k = tid + i*512;
                uint2 v = __ldcg(hsrc + k);
                *reinterpret_cast<uint2*>(HB + (size_t)k*8) = v;
            }
        }
        __syncthreads();

        // mma: 16 iters, B-frags only from smem, 4 interleaved chains
        {
            float cc[4][4];
            #pragma unroll
            for (int q = 0; q < 4; ++q)
                #pragma unroll
                for (int w = 0; w < 4; ++w) cc[q][w] = 0.f;
            #pragma unroll
            for (int ks = 0; ks < 16; ++ks) {
                unsigned b0, b1;
                ldsm2t(b0, b1, Bbase + (size_t)ks*128);
                mma16816(cc[ks & 3], af[ks], b0, b1);
            }
            #pragma unroll
            for (int w = 0; w < 4; ++w)
                cc[0][w] = (cc[0][w] + cc[1][w]) + (cc[2][w] + cc[3][w]);

            int r    = wr*16 + (lane >> 2);
            int ccol = (lane & 3)*2;
            float* Ck = Csm + kq*64*8;
            *reinterpret_cast<float2*>(&Ck[r*8 + ccol])     = make_float2(cc[0][0], cc[0][1]);
            *reinterpret_cast<float2*>(&Ck[(r+8)*8 + ccol]) = make_float2(cc[0][2], cc[0][3]);
        }
        __syncthreads();

        float hval = 0.f;
        if (fin) {
            int r0 = (lu*4+0)*8 + bb, r1 = (lu*4+1)*8 + bb;
            int r2 = (lu*4+2)*8 + bb, r3 = (lu*4+3)*8 + bb;
            float pi = (Csm[r0] + Csm[512+r0]) + (Csm[1024+r0] + Csm[1536+r0]) + pre.x;
            float pg = (Csm[r1] + Csm[512+r1]) + (Csm[1024+r1] + Csm[1536+r1]) + pre.y;
            float pf = (Csm[r2] + Csm[512+r2]) + (Csm[1024+r2] + Csm[1536+r2]) + pre.z;
            float po = (Csm[r3] + Csm[512+r3]) + (Csm[1024+r3] + Csm[1536+r3]) + pre.w;
            float ii = 1.f/(1.f + __expf(-pi));
            float gg = 2.f/(1.f + __expf(-2.f*pg)) - 1.f;
            float ff = 1.f/(1.f + __expf(-pf));
            float oo = 1.f/(1.f + __expf(-po));
            float c  = ff*creg + ii*gg;
            creg = c;
            float th = 2.f/(1.f + __expf(-2.f*c)) - 1.f;
            hval = oo * th;
            g_hc16[wb][d][(base + lu)*4 + bb] = __float2half_rn(hval);
        }
        grid_barrier_dir(d, blk, &localEpoch);
        // history store AFTER the flag release: off the critical sync path
        if (fin)
            hist[((size_t)bb*TT + t)*DD + base + lu] = hval;
    }
}

// ---------------- layer-1 input: x[b][t] = [hL[b][t], hR[b][T-1-t]] (fp16) -
__global__ void k_concat() {
    int idx = blockIdx.x * blockDim.x + threadIdx.x;    // float4 granularity
    const int total = BATCH*TT*(KINW/4);
    if (idx >= total) return;
    int c   = idx & (KINW/4 - 1);
    int row = idx >> 9;
    int b   = row >> 12;
    int t   = row & (TT-1);
    float4 v;
    if (c < DD/4) {
        v = reinterpret_cast<const float4*>(g_hL + ((size_t)b*TT + t)*DD)[c];
    } else {
        v = reinterpret_cast<const float4*>(g_hR + ((size_t)b*TT + (TT-1-t))*DD)[c - DD/4];
    }
    __half2* o = reinterpret_cast<__half2*>(g_xh) + (size_t)idx*2;
    o[0] = __floats2half2_rn(v.x, v.y);
    o[1] = __floats2half2_rn(v.z, v.w);
}

// ---------------- attention logits -----------------------------------------
__global__ void k_dots() {
    const int b = blockIdx.x >> 12;
    const int t = blockIdx.x & (TT-1);
    const int tid = threadIdx.x;
    const float* hl  = g_hL + ((size_t)b*TT + t)*DD;
    const float* hll = g_hL + ((size_t)b*TT + (TT-1))*DD;
    const float* hr  = g_hR + ((size_t)b*TT + t)*DD;
    const float* hrl = g_hR + ((size_t)b*TT + (TT-1))*DD;
    float s = 0.f;
    for (int j = tid; j < DD; j += 256)
        s += hl[j]*hll[j] + hr[j]*hrl[j];
    #pragma unroll
    for (int o=16;o>0;o>>=1) s += __shfl_xor_sync(0xffffffffu, s, o);
    __shared__ float red[8];
    if ((tid & 31) == 0) red[tid>>5] = s;
    __syncthreads();
    if (tid == 0) {
        float v = 0.f;
        #pragma unroll
        for (int w=0;w<8;w++) v += red[w];
        g_wv[(size_t)b*TT + t] = v * (1.f/64.f);   // 1/sqrt(4096)
    }
}

// ---------------- softmax per batch -----------------------------------------
__global__ void k_softmax() {
    const int b = blockIdx.x, tid = threadIdx.x;   // 1024 threads
    __shared__ float red[32];
    __shared__ float sval;
    const float* w = g_wv + (size_t)b*TT;
    float m = -1e30f;
    for (int t = tid; t < TT; t += 1024) m = fmaxf(m, w[t]);
    #pragma unroll
    for (int o=16;o>0;o>>=1) m = fmaxf(m, __shfl_xor_sync(0xffffffffu, m, o));
    if ((tid&31)==0) red[tid>>5] = m;
    __syncthreads();
    if (tid < 32) {
        float v = red[tid];
        #pragma unroll
        for (int o=16;o>0;o>>=1) v = fmaxf(v, __shfl_xor_sync(0xffffffffu, v, o));
        if (tid==0) sval = v;
    }
    __syncthreads();
    m = sval;
    float s = 0.f;
    for (int t = tid; t < TT; t += 1024) {
        float e = expf(w[t] - m);
        g_att[(size_t)b*TT + t] = e;
        s += e;
    }
    #pragma unroll
    for (int o=16;o>0;o>>=1) s += __shfl_xor_sync(0xffffffffu, s, o);
    __syncthreads();
    if ((tid&31)==0) red[tid>>5] = s;
    __syncthreads();
    if (tid < 32) {
        float v = red[tid];
        #pragma unroll
        for (int o=16;o>0;o>>=1) v += __shfl_xor_sync(0xffffffffu, v, o);
        if (tid==0) sval = v;
    }
    __syncthreads();
    float inv = 1.f / sval;
    for (int t = tid; t < TT; t += 1024)
        g_att[(size_t)b*TT + t] *= inv;
}

// ---------------- context vectors -------------------------------------------
__global__ void k_ctxt() {
    const int b = blockIdx.y;
    const int j = blockIdx.x*128 + threadIdx.x;
    const float* att = g_att + (size_t)b*TT;
    float aL = 0.f, aR = 0.f;
    for (int t = 0; t < TT; t += 4) {
        float a0 = att[t], a1 = att[t+1], a2 = att[t+2], a3 = att[t+3];
        const float* hl = g_hL + ((size_t)b*TT + t)*DD + j;
        const float* hr = g_hR + ((size_t)b*TT + t)*DD + j;
        aL += a0*hl[0] + a1*hl[DD] + a2*hl[2*DD] + a3*hl[3*DD];
        aR += a0*hr[0] + a1*hr[DD] + a2*hr[2*DD] + a3*hr[3*DD];
    }
    g_ctxtL[b*DD + j] = aL;
    g_ctxtR[b*DD + j] = aR;
}

// ---------------- output ----------------------------------------------------
__global__ void k_out(const float* __restrict__ WcyL, const float* __restrict__ WcyR,
                      float* __restrict__ out) {
    const int b = blockIdx.x;
    const int m = threadIdx.x >> 5;
    const int lane = threadIdx.x & 31;
    float s = 0.f;
    for (int j = lane; j < DD; j += 32)
        s += WcyL[m*DD + j]*g_ctxtL[b*DD + j] + WcyR[m*DD + j]*g_ctxtR[b*DD + j];
    #pragma unroll
    for (int o=16;o>0;o>>=1) s += __shfl_xor_sync(0xffffffffu, s, o);
    if (lane == 0) out[b*MOUT + m] = s;
}

// ---------------- launcher ---------------------------------------------------
extern "C" void kernel_launch(void* const* d_in, const int* in_sizes, int n_in,
                              void* d_out, int out_size) {
    const int*   toks = (const int*)  d_in[0];
    const float* emb  = (const float*)d_in[1];
    const float* Wxh  = (const float*)d_in[2];
    const float* Whh  = (const float*)d_in[3];
    const float* bxh  = (const float*)d_in[4];
    const float* bhh  = (const float*)d_in[5];
    const float* WcyL = (const float*)d_in[6];
    const float* WcyR = (const float*)d_in[7];
    float* out = (float*)d_out;
    (void)in_sizes; (void)n_in; (void)out_size;

    cudaFuncSetAttribute(k_recur, cudaFuncAttributeMaxDynamicSharedMemorySize,
                         SMEM_REC_BYTES);

    k_embed<<<(BATCH*TT*(EE/4) + 255)/256, 256>>>(toks, emb);
    k_whhr<<<(2*2*4096*512 + 255)/256, 256>>>(Whh);
    k_wx16<<<((2*2*GDIM*KINW)/4 + 255)/256, 256>>>(Wxh);

    for (int layer = 0; layer < 2; ++layer) {
        dim3 ggrid(GDIM/128, (BATCH*TT)/128, 2);
        k_gemm16<<<ggrid, 256>>>(bxh, bhh, layer);
        k_recur<<<RBLOCKS, RTHREADS, SMEM_REC_BYTES>>>(layer);
        if (layer == 0)
            k_concat<<<(BATCH*TT*(KINW/4) + 255)/256, 256>>>();
    }

    k_dots<<<BATCH*TT, 256>>>();
    k_softmax<<<BATCH, 1024>>>();
    dim3 cgrid(DD/128, BATCH);
    k_ctxt<<<cgrid, 128>>>();
    k_out<<<BATCH, 64>>>(WcyL, WcyR, out);
}